// round 11
// baseline (speedup 1.0000x reference)
#include <cuda_runtime.h>
#include <math.h>

#define NQ 4
#define DH 128
#define DIN 64
#define DOUT 32
#define PI_HALF 1.5707963267948966f
#define RSQRT2 0.7071067811865476f
#define FULL 0xffffffffu

#define MAXN 20000
#define MAXE 300000
#define MAXE2 (MAXN + MAXE)

// ---------------- scratch ----------------
__device__ float g_h[MAXN * DH];
__device__ float g_hn[MAXN * DH];
__device__ float g_xc[MAXN * DH];
__device__ float g_qtrig[MAXN * 8];   // per node: H-folded q amps a0..3 (bit=0), b0..3 (bit=1)
__device__ float g_ktrig[MAXN * 8];   // per node: cos k0..3, sin k0..3
__device__ float g_xq[MAXN * NQ];
__device__ float g_att[MAXE2];        // CSR-ordered exp(score)
__device__ float g_partial[4096];
__device__ float g_expsum;
__device__ unsigned g_ctr;            // last-block ticket (maintained at 0)
__device__ int   g_cnt[MAXN + 1];
__device__ int   g_off[MAXN + 1];
__device__ int   g_cur[MAXN];
__device__ int   g_chain[64];         // scan lookback chain (value = prefix+1; 0 = not ready)
__device__ int   g_src[MAXE2];        // CSR-ordered src node
__device__ int   g_dst[MAXE2];        // CSR-ordered dst node
__device__ float g_rot[36 * 8];       // [0..15] ent, [24..35] path
__device__ float g_attpre[2 * 8];     // per att layer: wZ[4], wX[4]
__device__ float g_M[DOUT * NQ];
__device__ float g_C[DOUT];

__device__ __forceinline__ float ftanh(float x)
{
    x = fmaxf(fminf(x, 15.f), -15.f);
    float t = __expf(2.f * x);
    return __fdividef(t - 1.f, t + 1.f);
}

// ---------------- setup ----------------
__global__ void setup_kernel(const float* __restrict__ ent, const float* __restrict__ attqp,
                             const float* __restrict__ path,
                             const float* __restrict__ poW, const float* __restrict__ pob,
                             const float* __restrict__ oW, const float* __restrict__ ob, int N)
{
    int gi = blockIdx.x * blockDim.x + threadIdx.x;
    if (gi <= N) g_cnt[gi] = 0;
    if (gi < 64) g_chain[gi] = 0;
    if (blockIdx.x != 0) return;
    int t = threadIdx.x;
    if (t < 36) {
        const float* p;
        if (t < 16)      p = ent + t * 3;
        else if (t < 24) p = attqp + (t - 16) * 3;
        else             p = path + (t - 24) * 3;
        float phi = p[0], th = p[1], om = p[2];
        float ct, st, ca, sa, cb, sb;
        sincosf(0.5f * th, &st, &ct);
        sincosf(0.5f * (phi + om), &sa, &ca);
        sincosf(0.5f * (phi - om), &sb, &cb);
        float* r = g_rot + t * 8;
        r[0] =  ct * ca; r[1] = -ct * sa;
        r[2] = -st * cb; r[3] = -st * sb;
        r[4] =  st * cb; r[5] = -st * sb;
        r[6] =  ct * ca; r[7] =  ct * sa;
    }
    // Rot^dag Z Rot = cos(th) Z - sin(th)(cos(phi) X - sin(phi) Y); real state => <Y>=0
    if (t == 40 || t == 41) {
        int l = t - 40;
        float* pre = g_attpre + l * 8;
        for (int i = 0; i < 4; i++) {
            float phi = attqp[l * 12 + i * 3 + 0];
            float th  = attqp[l * 12 + i * 3 + 1];
            float sth, cth;
            sincosf(th, &sth, &cth);
            pre[i]     = 0.25f * cth;
            pre[4 + i] = -0.5f * sth * cosf(phi);
        }
    }
    if (t >= 64 && t < 64 + DOUT) {
        int o = t - 64;
        float m0 = 0, m1 = 0, m2 = 0, m3 = 0, cc = 0;
        for (int j = 0; j < DH; j++) {
            float w = oW[o * DH + j];
            m0 += w * poW[j * NQ + 0];
            m1 += w * poW[j * NQ + 1];
            m2 += w * poW[j * NQ + 2];
            m3 += w * poW[j * NQ + 3];
            cc += w * pob[j];
        }
        g_M[o * NQ + 0] = m0; g_M[o * NQ + 1] = m1;
        g_M[o * NQ + 2] = m2; g_M[o * NQ + 3] = m3;
        g_C[o] = cc + ob[o];
    }
}

// ---------------- CSR build ----------------
__global__ void count_kernel(const int* __restrict__ ei, int E, int N)
{
    int e = blockIdx.x * blockDim.x + threadIdx.x;
    if (e >= E + N) return;
    int dst = (e < E) ? ei[E + e] : (e - E);
    atomicAdd(&g_cnt[dst], 1);
}

// single-kernel exclusive scan with chained lookback (blocks all resident: nb <= 20)
__global__ void scan_kernel(int N, int nb)
{
    __shared__ int wsum[32];
    __shared__ int sbase;
    int b = blockIdx.x;
    int i = b * 1024 + threadIdx.x;
    int lane = threadIdx.x & 31, wid = threadIdx.x >> 5;
    int v = (i < N) ? g_cnt[i] : 0;
    int s = v;
#pragma unroll
    for (int o = 1; o < 32; o <<= 1) {
        int t = __shfl_up_sync(FULL, s, o);
        if (lane >= o) s += t;
    }
    if (lane == 31) wsum[wid] = s;
    __syncthreads();
    if (wid == 0) {
        int ws = wsum[lane];
#pragma unroll
        for (int o = 1; o < 32; o <<= 1) {
            int t = __shfl_up_sync(FULL, ws, o);
            if (lane >= o) ws += t;
        }
        wsum[lane] = ws;
    }
    __syncthreads();
    int excl = s - v + (wid ? wsum[wid - 1] : 0);
    if (threadIdx.x == 0) {
        int x;
        if (b == 0) x = 1;
        else { while ((x = *(volatile int*)&g_chain[b - 1]) == 0) {} }
        sbase = x - 1;
    }
    __syncthreads();
    int base = sbase;
    if (i < N) { g_off[i] = base + excl; g_cur[i] = base + excl; }
    if (threadIdx.x == 1023) {
        int tot = base + excl + v;
        *(volatile int*)&g_chain[b] = tot + 1;
        if (b == nb - 1) g_off[N] = tot;
    }
}

__global__ void fill_kernel(const int* __restrict__ ei, int E, int N)
{
    int e = blockIdx.x * blockDim.x + threadIdx.x;
    if (e >= E + N) return;
    int src = (e < E) ? ei[e]     : (e - E);
    int dst = (e < E) ? ei[E + e] : (e - E);
    int pos = atomicAdd(&g_cur[dst], 1);
    g_src[pos] = src;
    g_dst[pos] = dst;
}

// ---------------- SGEMM 64x128 tile, 128 threads, 8x8 microkernel ----------------
__global__ __launch_bounds__(128)
void gemm64(const float* __restrict__ A, const float* __restrict__ W,
            const float* __restrict__ bias, float* __restrict__ C,
            int M, int K, int doRelu,
            const float* __restrict__ pW, const float* __restrict__ pb)
{
    __shared__ float As[16][64];
    __shared__ float Bs[16][128];
    int tid = threadIdx.x;
    int m0 = blockIdx.x * 64;
    int tx = tid & 15, ty = tid >> 4;

    float acc[8][8];
#pragma unroll
    for (int i = 0; i < 8; i++)
#pragma unroll
        for (int j = 0; j < 8; j++) acc[i][j] = 0.f;

    int ar = tid >> 1;
    int ac = (tid & 1) * 8;
    bool mok = (m0 + ar) < M;
    const float* ap = A + (size_t)(m0 + ar) * K + ac;
    const float* bp = W + (size_t)tid * K;

    float4 pa0, pa1, pb0, pb1, pb2, pb3;
    float4 z4 = make_float4(0.f, 0.f, 0.f, 0.f);
    pa0 = mok ? *(const float4*)(ap)     : z4;
    pa1 = mok ? *(const float4*)(ap + 4) : z4;
    pb0 = *(const float4*)(bp + 0);
    pb1 = *(const float4*)(bp + 4);
    pb2 = *(const float4*)(bp + 8);
    pb3 = *(const float4*)(bp + 12);

    for (int k0 = 0; k0 < K; k0 += 16) {
        __syncthreads();
        As[ac + 0][ar] = pa0.x; As[ac + 1][ar] = pa0.y;
        As[ac + 2][ar] = pa0.z; As[ac + 3][ar] = pa0.w;
        As[ac + 4][ar] = pa1.x; As[ac + 5][ar] = pa1.y;
        As[ac + 6][ar] = pa1.z; As[ac + 7][ar] = pa1.w;
        Bs[ 0][tid] = pb0.x; Bs[ 1][tid] = pb0.y; Bs[ 2][tid] = pb0.z; Bs[ 3][tid] = pb0.w;
        Bs[ 4][tid] = pb1.x; Bs[ 5][tid] = pb1.y; Bs[ 6][tid] = pb1.z; Bs[ 7][tid] = pb1.w;
        Bs[ 8][tid] = pb2.x; Bs[ 9][tid] = pb2.y; Bs[10][tid] = pb2.z; Bs[11][tid] = pb2.w;
        Bs[12][tid] = pb3.x; Bs[13][tid] = pb3.y; Bs[14][tid] = pb3.z; Bs[15][tid] = pb3.w;
        __syncthreads();
        if (k0 + 16 < K) {
            pa0 = mok ? *(const float4*)(ap + k0 + 16)     : z4;
            pa1 = mok ? *(const float4*)(ap + k0 + 16 + 4) : z4;
            pb0 = *(const float4*)(bp + k0 + 16);
            pb1 = *(const float4*)(bp + k0 + 20);
            pb2 = *(const float4*)(bp + k0 + 24);
            pb3 = *(const float4*)(bp + k0 + 28);
        }
#pragma unroll
        for (int kk = 0; kk < 16; kk++) {
            float4 ra0 = *(const float4*)&As[kk][ty * 4];
            float4 ra1 = *(const float4*)&As[kk][32 + ty * 4];
            float4 rb0 = *(const float4*)&Bs[kk][tx * 4];
            float4 rb1 = *(const float4*)&Bs[kk][64 + tx * 4];
            float a[8] = {ra0.x, ra0.y, ra0.z, ra0.w, ra1.x, ra1.y, ra1.z, ra1.w};
            float b[8] = {rb0.x, rb0.y, rb0.z, rb0.w, rb1.x, rb1.y, rb1.z, rb1.w};
#pragma unroll
            for (int i = 0; i < 8; i++)
#pragma unroll
                for (int j = 0; j < 8; j++) acc[i][j] += a[i] * b[j];
        }
    }

    float bb[8], pbv[8];
    float4 wcol[8];
#pragma unroll
    for (int j = 0; j < 8; j++) {
        int n = (j < 4) ? (tx * 4 + j) : (64 + tx * 4 + (j - 4));
        bb[j] = bias[n];
        if (pW) { wcol[j] = *(const float4*)(pW + n * NQ); pbv[j] = pb[n]; }
    }
#pragma unroll
    for (int i = 0; i < 8; i++) {
        int m = m0 + ((i < 4) ? (ty * 4 + i) : (32 + ty * 4 + (i - 4)));
        if (m < M) {
            float4 zz = z4;
            if (pW) zz = *(const float4*)(g_xq + m * NQ);
            float o[8];
#pragma unroll
            for (int j = 0; j < 8; j++) {
                float v = acc[i][j] + bb[j];
                if (pW) v += pbv[j] + zz.x * wcol[j].x + zz.y * wcol[j].y
                            + zz.z * wcol[j].z + zz.w * wcol[j].w;
                if (doRelu) v = fmaxf(v, 0.f);
                o[j] = v;
            }
            *(float4*)(C + (size_t)m * DH + tx * 4)      = make_float4(o[0], o[1], o[2], o[3]);
            *(float4*)(C + (size_t)m * DH + 64 + tx * 4) = make_float4(o[4], o[5], o[6], o[7]);
        }
    }
}

// ---------------- shuffle-based 16-lane statevector gates ----------------
__device__ __forceinline__ void cnot_shfl(float& ar, float& ai, int L, int mc, int mt)
{
    float pr = __shfl_xor_sync(FULL, ar, mt);
    float pi = __shfl_xor_sync(FULL, ai, mt);
    if (L & mc) { ar = pr; ai = pi; }
}

__device__ __forceinline__ void rot_shfl(float& ar, float& ai, int L, const float* __restrict__ u, int m)
{
    float pr = __shfl_xor_sync(FULL, ar, m);
    float pi = __shfl_xor_sync(FULL, ai, m);
    bool low = !(L & m);
    float owr = low ? u[0] : u[6], owi = low ? u[1] : u[7];
    float par = low ? u[2] : u[4], pai = low ? u[3] : u[5];
    float nr = owr * ar - owi * ai + par * pr - pai * pi;
    float ni = owr * ai + owi * ar + par * pi + pai * pr;
    ar = nr; ai = ni;
}

__device__ __forceinline__ void zexp_shfl(float ar, float ai, int L,
                                          float& z0, float& z1, float& z2, float& z3)
{
    float p = ar * ar + ai * ai;
    z0 = (L & 8) ? -p : p;
    z1 = (L & 4) ? -p : p;
    z2 = (L & 2) ? -p : p;
    z3 = (L & 1) ? -p : p;
#pragma unroll
    for (int o = 1; o < 16; o <<= 1) {
        z0 += __shfl_xor_sync(FULL, z0, o);
        z1 += __shfl_xor_sync(FULL, z1, o);
        z2 += __shfl_xor_sync(FULL, z2, o);
        z3 += __shfl_xor_sync(FULL, z3, o);
    }
}

// ---------------- fused per-node body: qk matvec + trig, ent circuit ----------------
__device__ __forceinline__ void node_body(float4 hv, int n, int lane, int rotbase,
                                          const float* __restrict__ qW, const float* __restrict__ qb,
                                          const float* __restrict__ kW, const float* __restrict__ kb)
{
    float acc[8];
#pragma unroll
    for (int i = 0; i < 4; i++) {
        float4 wq = *(const float4*)(qW + i * DH + lane * 4);
        acc[i] = hv.x * wq.x + hv.y * wq.y + hv.z * wq.z + hv.w * wq.w;
        float4 wk = *(const float4*)(kW + i * DH + lane * 4);
        acc[4 + i] = hv.x * wk.x + hv.y * wk.y + hv.z * wk.z + hv.w * wk.w;
    }
#pragma unroll
    for (int ofs = 16; ofs >= 1; ofs >>= 1)
#pragma unroll
        for (int i = 0; i < 8; i++) acc[i] += __shfl_xor_sync(FULL, acc[i], ofs);
    if (lane < 8) {
        float b = (lane < 4) ? qb[lane] : kb[lane - 4];
        float half = ftanh(acc[lane] + b) * (0.5f * PI_HALF);
        float s, c;
        __sincosf(half, &s, &c);
        if (lane < 4) {
            g_qtrig[n * 8 + lane]     = (c + s) * RSQRT2;   // bit = 0 (H folded)
            g_qtrig[n * 8 + 4 + lane] = (c - s) * RSQRT2;   // bit = 1
        } else {
            g_ktrig[n * 8 + lane - 4] = c;
            g_ktrig[n * 8 + lane]     = s;
        }
    }
    // ent circuit on lanes 0..15
    float h0 = __shfl_sync(FULL, hv.x, 0);
    float h1 = __shfl_sync(FULL, hv.y, 0);
    float h2 = __shfl_sync(FULL, hv.z, 0);
    float h3 = __shfl_sync(FULL, hv.w, 0);
    float myc = 1.f, mys = 0.f;
    if (lane < 4) {
        float myh = (lane == 0) ? h0 : (lane == 1) ? h1 : (lane == 2) ? h2 : h3;
        float a = ftanh(myh) * (0.5f * PI_HALF);
        __sincosf(a, &mys, &myc);
    }
    float c0 = __shfl_sync(FULL, myc, 0), s0 = __shfl_sync(FULL, mys, 0);
    float c1 = __shfl_sync(FULL, myc, 1), s1 = __shfl_sync(FULL, mys, 1);
    float c2 = __shfl_sync(FULL, myc, 2), s2 = __shfl_sync(FULL, mys, 2);
    float c3 = __shfl_sync(FULL, myc, 3), s3 = __shfl_sync(FULL, mys, 3);
    int L = lane & 15;
    float ar = (L & 8 ? s0 : c0) * (L & 4 ? s1 : c1) * (L & 2 ? s2 : c2) * (L & 1 ? s3 : c3);
    float ai = 0.f;
#pragma unroll
    for (int sub = 0; sub < 2; sub++) {
        cnot_shfl(ar, ai, L, 8, 4);
        cnot_shfl(ar, ai, L, 4, 2);
        cnot_shfl(ar, ai, L, 2, 1);
#pragma unroll
        for (int w = 0; w < 4; w++)
            rot_shfl(ar, ai, L, &g_rot[(rotbase + sub * 4 + w) * 8], 8 >> w);
        cnot_shfl(ar, ai, L, 8, 1);
    }
    float z0, z1, z2, z3;
    zexp_shfl(ar, ai, L, z0, z1, z2, z3);
    if (lane == 0)
        *(float4*)(g_xq + n * NQ) = make_float4(z0, z1, z2, z3);
}

__global__ void entqk_kernel(const float* __restrict__ h, int rotbase,
                             const float* __restrict__ qW, const float* __restrict__ qb,
                             const float* __restrict__ kW, const float* __restrict__ kb, int N)
{
    int warp = (blockIdx.x * blockDim.x + threadIdx.x) >> 5;
    int lane = threadIdx.x & 31;
    if (warp >= N) return;
    float4 hv = *(const float4*)(h + (size_t)warp * DH + lane * 4);
    node_body(hv, warp, lane, rotbase, qW, qb, kW, kb);
}

// ---------------- per-edge attention: CSR-slot order, observable-collapsed Rot ----------------
__global__ void edge_kernel(int E2, int layer)
{
    __shared__ float pre[8];
    if (threadIdx.x < 8) pre[threadIdx.x] = g_attpre[layer * 8 + threadIdx.x];
    __syncthreads();

    int e = blockIdx.x * blockDim.x + threadIdx.x;
    float wgt = 0.f;
    if (e < E2) {
        int src = g_src[e];
        int dst = g_dst[e];
        const float4* qp = (const float4*)(g_qtrig + src * 8);
        const float4* kp = (const float4*)(g_ktrig + dst * 8);
        float4 qa = qp[0], qb = qp[1];
        float4 kc = kp[0], ks = kp[1];
        float aa[4] = {qa.x, qa.y, qa.z, qa.w};
        float bb[4] = {qb.x, qb.y, qb.z, qb.w};
        float v[16];
#pragma unroll
        for (int idx = 0; idx < 16; idx++)
            v[idx] = (idx & 8 ? bb[0] : aa[0]) * (idx & 4 ? bb[1] : aa[1]) *
                     (idx & 2 ? bb[2] : aa[2]) * (idx & 1 ? bb[3] : aa[3]);
        float kcc[4] = {kc.x, kc.y, kc.z, kc.w};
        float kss[4] = {ks.x, ks.y, ks.z, ks.w};
#pragma unroll
        for (int i = 0; i < 4; i++) {
            float cs = kcc[i], sc = kss[i];
            int mc = 8 >> i, mt = 8 >> ((i + 1) & 3);
#pragma unroll
            for (int idx = 0; idx < 16; idx++) {
                if ((idx & mc) && !(idx & mt)) {
                    int j = idx | mt;
                    float a = v[idx], b = v[j];
                    v[idx] = cs * a - sc * b;
                    v[j]   = sc * a + cs * b;
                }
            }
        }
        float p[16];
#pragma unroll
        for (int idx = 0; idx < 16; idx++) p[idx] = v[idx] * v[idx];
        float score = 0.f;
#pragma unroll
        for (int i = 0; i < 4; i++) {
            int m = 8 >> i;
            float zs = 0.f, xs = 0.f;
#pragma unroll
            for (int idx = 0; idx < 16; idx++) {
                if (idx & m) zs -= p[idx];
                else { zs += p[idx]; xs += v[idx] * v[idx | m]; }
            }
            score += pre[i] * zs + pre[4 + i] * (2.f * xs);
        }
        wgt = __expf(score);
        g_att[e] = wgt;
    }
    __shared__ float sred[256];
    sred[threadIdx.x] = wgt;
    __syncthreads();
    for (int s = 128; s > 0; s >>= 1) {
        if (threadIdx.x < s) sred[threadIdx.x] += sred[threadIdx.x + s];
        __syncthreads();
    }
    if (threadIdx.x == 0) g_partial[blockIdx.x] = sred[0];

    __shared__ bool amLast;
    __threadfence();
    if (threadIdx.x == 0) {
        unsigned old = atomicAdd(&g_ctr, 1u);
        amLast = (old == gridDim.x - 1);
    }
    __syncthreads();
    if (amLast) {
        float a = 0.f;
        for (int i = threadIdx.x; i < gridDim.x; i += 256) a += g_partial[i];
        sred[threadIdx.x] = a;
        __syncthreads();
        for (int s = 128; s > 0; s >>= 1) {
            if (threadIdx.x < s) sred[threadIdx.x] += sred[threadIdx.x + s];
            __syncthreads();
        }
        if (threadIdx.x == 0) { g_expsum = sred[0]; g_ctr = 0u; }
    }
}

// ---------------- agg body ----------------
__device__ __forceinline__ float4 agg_row(int n, int lane)
{
    float inv = __frcp_rn(g_expsum);
    int beg = g_off[n], end = g_off[n + 1];
    float4 acc = make_float4(0.f, 0.f, 0.f, 0.f);
    int i = beg;
    for (; i + 3 < end; i += 4) {
        int   s0 = g_src[i],   s1 = g_src[i+1], s2 = g_src[i+2], s3 = g_src[i+3];
        float w0 = g_att[i],   w1 = g_att[i+1], w2 = g_att[i+2], w3 = g_att[i+3];
        float4 v0 = *(const float4*)(g_xc + (size_t)s0 * DH + lane * 4);
        float4 v1 = *(const float4*)(g_xc + (size_t)s1 * DH + lane * 4);
        float4 v2 = *(const float4*)(g_xc + (size_t)s2 * DH + lane * 4);
        float4 v3 = *(const float4*)(g_xc + (size_t)s3 * DH + lane * 4);
        acc.x += w0*v0.x + w1*v1.x + w2*v2.x + w3*v3.x;
        acc.y += w0*v0.y + w1*v1.y + w2*v2.y + w3*v3.y;
        acc.z += w0*v0.z + w1*v1.z + w2*v2.z + w3*v3.z;
        acc.w += w0*v0.w + w1*v1.w + w2*v2.w + w3*v3.w;
    }
    for (; i < end; i++) {
        float w = g_att[i];
        float4 v = *(const float4*)(g_xc + (size_t)g_src[i] * DH + lane * 4);
        acc.x += w*v.x; acc.y += w*v.y; acc.z += w*v.z; acc.w += w*v.w;
    }
    float4 o;
    o.x = fmaxf(acc.x * inv, 0.f);
    o.y = fmaxf(acc.y * inv, 0.f);
    o.z = fmaxf(acc.z * inv, 0.f);
    o.w = fmaxf(acc.w * inv, 0.f);
    return o;
}

// ---------------- agg + entqk fused ----------------
__global__ void aggentqk_kernel(float* __restrict__ hout, int rotbase,
                                const float* __restrict__ qW, const float* __restrict__ qb,
                                const float* __restrict__ kW, const float* __restrict__ kb, int N)
{
    int warp = (blockIdx.x * blockDim.x + threadIdx.x) >> 5;
    int lane = threadIdx.x & 31;
    if (warp >= N) return;
    float4 hv = agg_row(warp, lane);
    *(float4*)(hout + (size_t)warp * DH + lane * 4) = hv;
    node_body(hv, warp, lane, rotbase, qW, qb, kW, kb);
}

// ---------------- agg + final path circuit fused ----------------
__global__ void aggfinal_kernel(const float* __restrict__ piW, const float* __restrict__ pib,
                                float* __restrict__ out, int N)
{
    int warp = (blockIdx.x * blockDim.x + threadIdx.x) >> 5;
    int lane = threadIdx.x & 31;
    if (warp >= N) return;
    float4 hv = agg_row(warp, lane);

    float acc[4];
#pragma unroll
    for (int i = 0; i < 4; i++) {
        float4 w = *(const float4*)(piW + i * DH + lane * 4);
        acc[i] = hv.x * w.x + hv.y * w.y + hv.z * w.z + hv.w * w.w;
    }
#pragma unroll
    for (int ofs = 16; ofs >= 1; ofs >>= 1)
#pragma unroll
        for (int i = 0; i < 4; i++) acc[i] += __shfl_xor_sync(FULL, acc[i], ofs);

    float myb0 = 0.f, myb1 = 0.f;
    if (lane < 4) {
        float a = ftanh(acc[lane] + pib[lane]) * (0.5f * PI_HALF);
        float s, c;
        __sincosf(a, &s, &c);
        myb0 = (c - s) * RSQRT2;
        myb1 = (c + s) * RSQRT2;
    }
    float b00 = __shfl_sync(FULL, myb0, 0), b10 = __shfl_sync(FULL, myb1, 0);
    float b01 = __shfl_sync(FULL, myb0, 1), b11 = __shfl_sync(FULL, myb1, 1);
    float b02 = __shfl_sync(FULL, myb0, 2), b12 = __shfl_sync(FULL, myb1, 2);
    float b03 = __shfl_sync(FULL, myb0, 3), b13 = __shfl_sync(FULL, myb1, 3);
    int L = lane & 15;
    float ar = (L & 8 ? b10 : b00) * (L & 4 ? b11 : b01) * (L & 2 ? b12 : b02) * (L & 1 ? b13 : b03);
    float ai = 0.f;
#pragma unroll
    for (int l = 0; l < 3; l++) {
#pragma unroll
        for (int w = 0; w < 4; w++)
            rot_shfl(ar, ai, L, &g_rot[(24 + l * 4 + w) * 8], 8 >> w);
        cnot_shfl(ar, ai, L, 8, 4);
        cnot_shfl(ar, ai, L, 4, 2);
        cnot_shfl(ar, ai, L, 2, 1);
    }
    float z0, z1, z2, z3;
    zexp_shfl(ar, ai, L, z0, z1, z2, z3);
    z0 = __shfl_sync(FULL, z0, 0);
    z1 = __shfl_sync(FULL, z1, 0);
    z2 = __shfl_sync(FULL, z2, 0);
    z3 = __shfl_sync(FULL, z3, 0);
    float4 m = *(const float4*)(g_M + lane * 4);
    out[(size_t)warp * DOUT + lane] = z0 * m.x + z1 * m.y + z2 * m.z + z3 * m.w + g_C[lane];
}

// ---------------- host ----------------
extern "C" void kernel_launch(void* const* d_in, const int* in_sizes, int n_in,
                              void* d_out, int out_size)
{
    const float* x          = (const float*)d_in[0];
    const float* W_in       = (const float*)d_in[1];
    const float* b_in       = (const float*)d_in[2];
    const float* lin_W      = (const float*)d_in[3];
    const float* lin_b      = (const float*)d_in[4];
    const float* qproj_W    = (const float*)d_in[5];
    const float* qproj_b    = (const float*)d_in[6];
    const float* ent_params = (const float*)d_in[7];
    const float* attq_W     = (const float*)d_in[8];
    const float* attq_b     = (const float*)d_in[9];
    const float* attk_W     = (const float*)d_in[10];
    const float* attk_b     = (const float*)d_in[11];
    const float* att_qp     = (const float*)d_in[12];
    const float* path_params= (const float*)d_in[13];
    const float* path_in_W  = (const float*)d_in[14];
    const float* path_in_b  = (const float*)d_in[15];
    const float* path_out_W = (const float*)d_in[16];
    const float* path_out_b = (const float*)d_in[17];
    const float* out_W      = (const float*)d_in[18];
    const float* out_b      = (const float*)d_in[19];
    const int*   edge_index = (const int*)d_in[20];
    float* out = (float*)d_out;

    int N  = in_sizes[0] / DIN;
    int E  = in_sizes[20] / 2;
    int E2 = E + N;

    float *p_h, *p_hn, *p_xc;
    cudaGetSymbolAddress((void**)&p_h,  g_h);
    cudaGetSymbolAddress((void**)&p_hn, g_hn);
    cudaGetSymbolAddress((void**)&p_xc, g_xc);

    // side stream + fork/join events (created once; resource handles only, no device mem)
    static cudaStream_t sB = nullptr;
    static cudaEvent_t evFork = nullptr, evQK0, evEdge0, evQK1, evEdge1;
    if (sB == nullptr) {
        cudaStreamCreateWithFlags(&sB, cudaStreamNonBlocking);
        cudaEventCreateWithFlags(&evFork,  cudaEventDisableTiming);
        cudaEventCreateWithFlags(&evQK0,   cudaEventDisableTiming);
        cudaEventCreateWithFlags(&evEdge0, cudaEventDisableTiming);
        cudaEventCreateWithFlags(&evQK1,   cudaEventDisableTiming);
        cudaEventCreateWithFlags(&evEdge1, cudaEventDisableTiming);
    }

    int eblocks = (E2 + 255) / 256;
    int sblocks = (N + 1023) / 1024;

    // setup on main stream, then fork CSR chain onto sB
    setup_kernel<<<(N + 256) / 256, 256>>>(ent_params, att_qp, path_params,
                                           path_out_W, path_out_b, out_W, out_b, N);
    cudaEventRecord(evFork, 0);
    cudaStreamWaitEvent(sB, evFork, 0);

    // chain B: CSR build
    count_kernel<<<eblocks, 256, 0, sB>>>(edge_index, E, N);
    scan_kernel<<<sblocks, 1024, 0, sB>>>(N, sblocks);
    fill_kernel<<<eblocks, 256, 0, sB>>>(edge_index, E, N);

    // chain A: gemm_in -> entqk0
    gemm64<<<(N + 63) / 64, 128>>>(x, W_in, b_in, p_h, N, DIN, 1, nullptr, nullptr);
    entqk_kernel<<<(N + 7) / 8, 256>>>(p_h, 0, attq_W, attq_b, attk_W, attk_b, N);
    cudaEventRecord(evQK0, 0);
    cudaStreamWaitEvent(sB, evQK0, 0);

    // overlap: gemm_lin0 (A) || edge0 (B)
    gemm64<<<(N + 63) / 64, 128>>>(p_h, lin_W, lin_b, p_xc, N, DH, 0, qproj_W, qproj_b);
    edge_kernel<<<eblocks, 256, 0, sB>>>(E2, 0);
    cudaEventRecord(evEdge0, sB);
    cudaStreamWaitEvent(0, evEdge0, 0);

    // layer 1: agg+entqk on A
    aggentqk_kernel<<<(N + 7) / 8, 256>>>(p_hn, 8,
                                          attq_W + NQ * DH, attq_b + NQ,
                                          attk_W + NQ * DH, attk_b + NQ, N);
    cudaEventRecord(evQK1, 0);
    cudaStreamWaitEvent(sB, evQK1, 0);

    // overlap: gemm_lin1 (A) || edge1 (B)
    gemm64<<<(N + 63) / 64, 128>>>(p_hn, lin_W + (size_t)DH * DH, lin_b + DH, p_xc, N, DH, 0,
                                   qproj_W + (size_t)DH * NQ, qproj_b + DH);
    edge_kernel<<<eblocks, 256, 0, sB>>>(E2, 1);
    cudaEventRecord(evEdge1, sB);
    cudaStreamWaitEvent(0, evEdge1, 0);

    // final
    aggfinal_kernel<<<(N + 7) / 8, 256>>>(path_in_W, path_in_b, out, N);
}

// round 13
// speedup vs baseline: 1.0593x; 1.0593x over previous
#include <cuda_runtime.h>
#include <math.h>

#define NQ 4
#define DH 128
#define DIN 64
#define DOUT 32
#define PI_HALF 1.5707963267948966f
#define RSQRT2 0.7071067811865476f
#define FULL 0xffffffffu

#define MAXN 20000
#define MAXE 300000
#define MAXE2 (MAXN + MAXE)

// ---------------- scratch ----------------
__device__ float g_h[MAXN * DH];
__device__ float g_hn[MAXN * DH];
__device__ float g_xc[MAXN * DH];
__device__ float g_qtrig[MAXN * 8];   // per node: H-folded q amps a0..3 (bit=0), b0..3 (bit=1)
__device__ float g_ktrig[MAXN * 8];   // per node: cos k0..3, sin k0..3
__device__ float g_xq[MAXN * NQ];
__device__ float g_att[MAXE2];        // CSR-ordered exp(score)
__device__ float g_partial[4096];
__device__ float g_expsum;
__device__ unsigned g_ctr;            // last-block ticket (maintained at 0)
__device__ int   g_cnt[MAXN + 1];
__device__ int   g_off[MAXN + 1];
__device__ int   g_cur[MAXN];
__device__ int   g_chain[64];         // scan lookback chain (value = prefix+1; 0 = not ready)
__device__ int   g_src[MAXE2];        // CSR-ordered src node
__device__ int   g_dst[MAXE2];        // CSR-ordered dst node
__device__ unsigned g_gen;            // grid barrier generation
__device__ unsigned g_arrive;         // grid barrier arrival count
__device__ float g_rot[36 * 8];       // [0..15] ent, [24..35] path
__device__ float g_attpre[2 * 8];     // per att layer: wZ[4], wX[4]
__device__ float g_M[DOUT * NQ];
__device__ float g_C[DOUT];

__device__ __forceinline__ float ftanh(float x)
{
    x = fmaxf(fminf(x, 15.f), -15.f);
    float t = __expf(2.f * x);
    return __fdividef(t - 1.f, t + 1.f);
}

// ---------------- setup ----------------
__global__ void setup_kernel(const float* __restrict__ ent, const float* __restrict__ attqp,
                             const float* __restrict__ path,
                             const float* __restrict__ poW, const float* __restrict__ pob,
                             const float* __restrict__ oW, const float* __restrict__ ob, int N)
{
    int gi = blockIdx.x * blockDim.x + threadIdx.x;
    if (gi <= N) g_cnt[gi] = 0;
    if (gi < 64) g_chain[gi] = 0;
    if (blockIdx.x != 0) return;
    int t = threadIdx.x;
    if (t < 36) {
        const float* p;
        if (t < 16)      p = ent + t * 3;
        else if (t < 24) p = attqp + (t - 16) * 3;
        else             p = path + (t - 24) * 3;
        float phi = p[0], th = p[1], om = p[2];
        float ct, st, ca, sa, cb, sb;
        sincosf(0.5f * th, &st, &ct);
        sincosf(0.5f * (phi + om), &sa, &ca);
        sincosf(0.5f * (phi - om), &sb, &cb);
        float* r = g_rot + t * 8;
        r[0] =  ct * ca; r[1] = -ct * sa;
        r[2] = -st * cb; r[3] = -st * sb;
        r[4] =  st * cb; r[5] = -st * sb;
        r[6] =  ct * ca; r[7] =  ct * sa;
    }
    // Rot^dag Z Rot = cos(th) Z - sin(th)(cos(phi) X - sin(phi) Y); real state => <Y>=0
    if (t == 40 || t == 41) {
        int l = t - 40;
        float* pre = g_attpre + l * 8;
        for (int i = 0; i < 4; i++) {
            float phi = attqp[l * 12 + i * 3 + 0];
            float th  = attqp[l * 12 + i * 3 + 1];
            float sth, cth;
            sincosf(th, &sth, &cth);
            pre[i]     = 0.25f * cth;
            pre[4 + i] = -0.5f * sth * cosf(phi);
        }
    }
    if (t >= 64 && t < 64 + DOUT) {
        int o = t - 64;
        float m0 = 0, m1 = 0, m2 = 0, m3 = 0, cc = 0;
        for (int j = 0; j < DH; j++) {
            float w = oW[o * DH + j];
            m0 += w * poW[j * NQ + 0];
            m1 += w * poW[j * NQ + 1];
            m2 += w * poW[j * NQ + 2];
            m3 += w * poW[j * NQ + 3];
            cc += w * pob[j];
        }
        g_M[o * NQ + 0] = m0; g_M[o * NQ + 1] = m1;
        g_M[o * NQ + 2] = m2; g_M[o * NQ + 3] = m3;
        g_C[o] = cc + ob[o];
    }
}

// ---------------- software grid barrier (all nb blocks resident; nb <= 20) ----------------
__device__ __forceinline__ void grid_barrier(int nb)
{
    __syncthreads();
    if (threadIdx.x == 0) {
        __threadfence();
        unsigned mygen = *(volatile unsigned*)&g_gen;
        unsigned old = atomicAdd(&g_arrive, 1u);
        if (old == (unsigned)nb - 1) {
            g_arrive = 0;
            __threadfence();
            atomicExch(&g_gen, mygen + 1);
        } else {
            while (*(volatile unsigned*)&g_gen == mygen) { __nanosleep(32); }
        }
        __threadfence();
    }
    __syncthreads();
}

// ---------------- fused CSR build: count -> scan -> fill, one kernel ----------------
__global__ __launch_bounds__(1024)
void csr_build_kernel(const int* __restrict__ ei, int E, int N, int nb)
{
    int tid = threadIdx.x;
    int b = blockIdx.x;
    int gthreads = nb * 1024;
    int gtid = b * 1024 + tid;
    int E2 = E + N;

    // phase 1: count (grid-stride)
    for (int e = gtid; e < E2; e += gthreads) {
        int dst = (e < E) ? ei[E + e] : (e - E);
        atomicAdd(&g_cnt[dst], 1);
    }
    grid_barrier(nb);

    // phase 2: exclusive scan with chained lookback (one element per thread; nb*1024 >= N)
    {
        __shared__ int wsum[32];
        __shared__ int sbase;
        int i = gtid;
        int lane = tid & 31, wid = tid >> 5;
        int v = (i < N) ? g_cnt[i] : 0;
        int s = v;
#pragma unroll
        for (int o = 1; o < 32; o <<= 1) {
            int t = __shfl_up_sync(FULL, s, o);
            if (lane >= o) s += t;
        }
        if (lane == 31) wsum[wid] = s;
        __syncthreads();
        if (wid == 0) {
            int ws = wsum[lane];
#pragma unroll
            for (int o = 1; o < 32; o <<= 1) {
                int t = __shfl_up_sync(FULL, ws, o);
                if (lane >= o) ws += t;
            }
            wsum[lane] = ws;
        }
        __syncthreads();
        int excl = s - v + (wid ? wsum[wid - 1] : 0);
        if (tid == 0) {
            int x;
            if (b == 0) x = 1;
            else { while ((x = *(volatile int*)&g_chain[b - 1]) == 0) { __nanosleep(32); } }
            sbase = x - 1;
        }
        __syncthreads();
        int base = sbase;
        if (i < N) { g_off[i] = base + excl; g_cur[i] = base + excl; }
        if (tid == 1023) {
            int tot = base + excl + v;
            __threadfence();
            *(volatile int*)&g_chain[b] = tot + 1;
            if (b == nb - 1) g_off[N] = tot;
        }
    }
    grid_barrier(nb);

    // phase 3: fill (grid-stride; independent iterations give MLP)
    for (int e = gtid; e < E2; e += gthreads) {
        int src = (e < E) ? ei[e]     : (e - E);
        int dst = (e < E) ? ei[E + e] : (e - E);
        int pos = atomicAdd(&g_cur[dst], 1);
        g_src[pos] = src;
        g_dst[pos] = dst;
    }
}

// ---------------- SGEMM 64x128 tile, 128 threads, 8x8 microkernel ----------------
__global__ __launch_bounds__(128)
void gemm64(const float* __restrict__ A, const float* __restrict__ W,
            const float* __restrict__ bias, float* __restrict__ C,
            int M, int K, int doRelu,
            const float* __restrict__ pW, const float* __restrict__ pb)
{
    __shared__ float As[16][64];
    __shared__ float Bs[16][128];
    int tid = threadIdx.x;
    int m0 = blockIdx.x * 64;
    int tx = tid & 15, ty = tid >> 4;

    float acc[8][8];
#pragma unroll
    for (int i = 0; i < 8; i++)
#pragma unroll
        for (int j = 0; j < 8; j++) acc[i][j] = 0.f;

    int ar = tid >> 1;
    int ac = (tid & 1) * 8;
    bool mok = (m0 + ar) < M;
    const float* ap = A + (size_t)(m0 + ar) * K + ac;
    const float* bp = W + (size_t)tid * K;

    float4 pa0, pa1, pb0, pb1, pb2, pb3;
    float4 z4 = make_float4(0.f, 0.f, 0.f, 0.f);
    pa0 = mok ? *(const float4*)(ap)     : z4;
    pa1 = mok ? *(const float4*)(ap + 4) : z4;
    pb0 = *(const float4*)(bp + 0);
    pb1 = *(const float4*)(bp + 4);
    pb2 = *(const float4*)(bp + 8);
    pb3 = *(const float4*)(bp + 12);

    for (int k0 = 0; k0 < K; k0 += 16) {
        __syncthreads();
        As[ac + 0][ar] = pa0.x; As[ac + 1][ar] = pa0.y;
        As[ac + 2][ar] = pa0.z; As[ac + 3][ar] = pa0.w;
        As[ac + 4][ar] = pa1.x; As[ac + 5][ar] = pa1.y;
        As[ac + 6][ar] = pa1.z; As[ac + 7][ar] = pa1.w;
        Bs[ 0][tid] = pb0.x; Bs[ 1][tid] = pb0.y; Bs[ 2][tid] = pb0.z; Bs[ 3][tid] = pb0.w;
        Bs[ 4][tid] = pb1.x; Bs[ 5][tid] = pb1.y; Bs[ 6][tid] = pb1.z; Bs[ 7][tid] = pb1.w;
        Bs[ 8][tid] = pb2.x; Bs[ 9][tid] = pb2.y; Bs[10][tid] = pb2.z; Bs[11][tid] = pb2.w;
        Bs[12][tid] = pb3.x; Bs[13][tid] = pb3.y; Bs[14][tid] = pb3.z; Bs[15][tid] = pb3.w;
        __syncthreads();
        if (k0 + 16 < K) {
            pa0 = mok ? *(const float4*)(ap + k0 + 16)     : z4;
            pa1 = mok ? *(const float4*)(ap + k0 + 16 + 4) : z4;
            pb0 = *(const float4*)(bp + k0 + 16);
            pb1 = *(const float4*)(bp + k0 + 20);
            pb2 = *(const float4*)(bp + k0 + 24);
            pb3 = *(const float4*)(bp + k0 + 28);
        }
#pragma unroll
        for (int kk = 0; kk < 16; kk++) {
            float4 ra0 = *(const float4*)&As[kk][ty * 4];
            float4 ra1 = *(const float4*)&As[kk][32 + ty * 4];
            float4 rb0 = *(const float4*)&Bs[kk][tx * 4];
            float4 rb1 = *(const float4*)&Bs[kk][64 + tx * 4];
            float a[8] = {ra0.x, ra0.y, ra0.z, ra0.w, ra1.x, ra1.y, ra1.z, ra1.w};
            float b[8] = {rb0.x, rb0.y, rb0.z, rb0.w, rb1.x, rb1.y, rb1.z, rb1.w};
#pragma unroll
            for (int i = 0; i < 8; i++)
#pragma unroll
                for (int j = 0; j < 8; j++) acc[i][j] += a[i] * b[j];
        }
    }

    float bb[8], pbv[8];
    float4 wcol[8];
#pragma unroll
    for (int j = 0; j < 8; j++) {
        int n = (j < 4) ? (tx * 4 + j) : (64 + tx * 4 + (j - 4));
        bb[j] = bias[n];
        if (pW) { wcol[j] = *(const float4*)(pW + n * NQ); pbv[j] = pb[n]; }
    }
#pragma unroll
    for (int i = 0; i < 8; i++) {
        int m = m0 + ((i < 4) ? (ty * 4 + i) : (32 + ty * 4 + (i - 4)));
        if (m < M) {
            float4 zz = z4;
            if (pW) zz = *(const float4*)(g_xq + m * NQ);
            float o[8];
#pragma unroll
            for (int j = 0; j < 8; j++) {
                float v = acc[i][j] + bb[j];
                if (pW) v += pbv[j] + zz.x * wcol[j].x + zz.y * wcol[j].y
                            + zz.z * wcol[j].z + zz.w * wcol[j].w;
                if (doRelu) v = fmaxf(v, 0.f);
                o[j] = v;
            }
            *(float4*)(C + (size_t)m * DH + tx * 4)      = make_float4(o[0], o[1], o[2], o[3]);
            *(float4*)(C + (size_t)m * DH + 64 + tx * 4) = make_float4(o[4], o[5], o[6], o[7]);
        }
    }
}

// ---------------- shuffle-based 16-lane statevector gates ----------------
__device__ __forceinline__ void cnot_shfl(float& ar, float& ai, int L, int mc, int mt)
{
    float pr = __shfl_xor_sync(FULL, ar, mt);
    float pi = __shfl_xor_sync(FULL, ai, mt);
    if (L & mc) { ar = pr; ai = pi; }
}

__device__ __forceinline__ void rot_shfl(float& ar, float& ai, int L, const float* __restrict__ u, int m)
{
    float pr = __shfl_xor_sync(FULL, ar, m);
    float pi = __shfl_xor_sync(FULL, ai, m);
    bool low = !(L & m);
    float owr = low ? u[0] : u[6], owi = low ? u[1] : u[7];
    float par = low ? u[2] : u[4], pai = low ? u[3] : u[5];
    float nr = owr * ar - owi * ai + par * pr - pai * pi;
    float ni = owr * ai + owi * ar + par * pi + pai * pr;
    ar = nr; ai = ni;
}

__device__ __forceinline__ void zexp_shfl(float ar, float ai, int L,
                                          float& z0, float& z1, float& z2, float& z3)
{
    float p = ar * ar + ai * ai;
    z0 = (L & 8) ? -p : p;
    z1 = (L & 4) ? -p : p;
    z2 = (L & 2) ? -p : p;
    z3 = (L & 1) ? -p : p;
#pragma unroll
    for (int o = 1; o < 16; o <<= 1) {
        z0 += __shfl_xor_sync(FULL, z0, o);
        z1 += __shfl_xor_sync(FULL, z1, o);
        z2 += __shfl_xor_sync(FULL, z2, o);
        z3 += __shfl_xor_sync(FULL, z3, o);
    }
}

// ---------------- fused per-node body: qk matvec + trig, ent circuit ----------------
__device__ __forceinline__ void node_body(float4 hv, int n, int lane, int rotbase,
                                          const float* __restrict__ qW, const float* __restrict__ qb,
                                          const float* __restrict__ kW, const float* __restrict__ kb)
{
    float acc[8];
#pragma unroll
    for (int i = 0; i < 4; i++) {
        float4 wq = *(const float4*)(qW + i * DH + lane * 4);
        acc[i] = hv.x * wq.x + hv.y * wq.y + hv.z * wq.z + hv.w * wq.w;
        float4 wk = *(const float4*)(kW + i * DH + lane * 4);
        acc[4 + i] = hv.x * wk.x + hv.y * wk.y + hv.z * wk.z + hv.w * wk.w;
    }
#pragma unroll
    for (int ofs = 16; ofs >= 1; ofs >>= 1)
#pragma unroll
        for (int i = 0; i < 8; i++) acc[i] += __shfl_xor_sync(FULL, acc[i], ofs);
    if (lane < 8) {
        float b = (lane < 4) ? qb[lane] : kb[lane - 4];
        float half = ftanh(acc[lane] + b) * (0.5f * PI_HALF);
        float s, c;
        __sincosf(half, &s, &c);
        if (lane < 4) {
            g_qtrig[n * 8 + lane]     = (c + s) * RSQRT2;   // bit = 0 (H folded)
            g_qtrig[n * 8 + 4 + lane] = (c - s) * RSQRT2;   // bit = 1
        } else {
            g_ktrig[n * 8 + lane - 4] = c;
            g_ktrig[n * 8 + lane]     = s;
        }
    }
    // ent circuit on lanes 0..15
    float h0 = __shfl_sync(FULL, hv.x, 0);
    float h1 = __shfl_sync(FULL, hv.y, 0);
    float h2 = __shfl_sync(FULL, hv.z, 0);
    float h3 = __shfl_sync(FULL, hv.w, 0);
    float myc = 1.f, mys = 0.f;
    if (lane < 4) {
        float myh = (lane == 0) ? h0 : (lane == 1) ? h1 : (lane == 2) ? h2 : h3;
        float a = ftanh(myh) * (0.5f * PI_HALF);
        __sincosf(a, &mys, &myc);
    }
    float c0 = __shfl_sync(FULL, myc, 0), s0 = __shfl_sync(FULL, mys, 0);
    float c1 = __shfl_sync(FULL, myc, 1), s1 = __shfl_sync(FULL, mys, 1);
    float c2 = __shfl_sync(FULL, myc, 2), s2 = __shfl_sync(FULL, mys, 2);
    float c3 = __shfl_sync(FULL, myc, 3), s3 = __shfl_sync(FULL, mys, 3);
    int L = lane & 15;
    float ar = (L & 8 ? s0 : c0) * (L & 4 ? s1 : c1) * (L & 2 ? s2 : c2) * (L & 1 ? s3 : c3);
    float ai = 0.f;
#pragma unroll
    for (int sub = 0; sub < 2; sub++) {
        cnot_shfl(ar, ai, L, 8, 4);
        cnot_shfl(ar, ai, L, 4, 2);
        cnot_shfl(ar, ai, L, 2, 1);
#pragma unroll
        for (int w = 0; w < 4; w++)
            rot_shfl(ar, ai, L, &g_rot[(rotbase + sub * 4 + w) * 8], 8 >> w);
        cnot_shfl(ar, ai, L, 8, 1);
    }
    float z0, z1, z2, z3;
    zexp_shfl(ar, ai, L, z0, z1, z2, z3);
    if (lane == 0)
        *(float4*)(g_xq + n * NQ) = make_float4(z0, z1, z2, z3);
}

__global__ void entqk_kernel(const float* __restrict__ h, int rotbase,
                             const float* __restrict__ qW, const float* __restrict__ qb,
                             const float* __restrict__ kW, const float* __restrict__ kb, int N)
{
    int warp = (blockIdx.x * blockDim.x + threadIdx.x) >> 5;
    int lane = threadIdx.x & 31;
    if (warp >= N) return;
    float4 hv = *(const float4*)(h + (size_t)warp * DH + lane * 4);
    node_body(hv, warp, lane, rotbase, qW, qb, kW, kb);
}

// ---------------- per-edge attention: CSR-slot order, observable-collapsed Rot ----------------
__global__ void edge_kernel(int E2, int layer)
{
    __shared__ float pre[8];
    if (threadIdx.x < 8) pre[threadIdx.x] = g_attpre[layer * 8 + threadIdx.x];
    __syncthreads();

    int e = blockIdx.x * blockDim.x + threadIdx.x;
    float wgt = 0.f;
    if (e < E2) {
        int src = g_src[e];
        int dst = g_dst[e];
        const float4* qp = (const float4*)(g_qtrig + src * 8);
        const float4* kp = (const float4*)(g_ktrig + dst * 8);
        float4 qa = qp[0], qb = qp[1];
        float4 kc = kp[0], ks = kp[1];
        float aa[4] = {qa.x, qa.y, qa.z, qa.w};
        float bb[4] = {qb.x, qb.y, qb.z, qb.w};
        float v[16];
#pragma unroll
        for (int idx = 0; idx < 16; idx++)
            v[idx] = (idx & 8 ? bb[0] : aa[0]) * (idx & 4 ? bb[1] : aa[1]) *
                     (idx & 2 ? bb[2] : aa[2]) * (idx & 1 ? bb[3] : aa[3]);
        float kcc[4] = {kc.x, kc.y, kc.z, kc.w};
        float kss[4] = {ks.x, ks.y, ks.z, ks.w};
#pragma unroll
        for (int i = 0; i < 4; i++) {
            float cs = kcc[i], sc = kss[i];
            int mc = 8 >> i, mt = 8 >> ((i + 1) & 3);
#pragma unroll
            for (int idx = 0; idx < 16; idx++) {
                if ((idx & mc) && !(idx & mt)) {
                    int j = idx | mt;
                    float a = v[idx], b = v[j];
                    v[idx] = cs * a - sc * b;
                    v[j]   = sc * a + cs * b;
                }
            }
        }
        float p[16];
#pragma unroll
        for (int idx = 0; idx < 16; idx++) p[idx] = v[idx] * v[idx];
        float score = 0.f;
#pragma unroll
        for (int i = 0; i < 4; i++) {
            int m = 8 >> i;
            float zs = 0.f, xs = 0.f;
#pragma unroll
            for (int idx = 0; idx < 16; idx++) {
                if (idx & m) zs -= p[idx];
                else { zs += p[idx]; xs += v[idx] * v[idx | m]; }
            }
            score += pre[i] * zs + pre[4 + i] * (2.f * xs);
        }
        wgt = __expf(score);
        g_att[e] = wgt;
    }
    __shared__ float sred[256];
    sred[threadIdx.x] = wgt;
    __syncthreads();
    for (int s = 128; s > 0; s >>= 1) {
        if (threadIdx.x < s) sred[threadIdx.x] += sred[threadIdx.x + s];
        __syncthreads();
    }
    if (threadIdx.x == 0) g_partial[blockIdx.x] = sred[0];

    __shared__ bool amLast;
    __threadfence();
    if (threadIdx.x == 0) {
        unsigned old = atomicAdd(&g_ctr, 1u);
        amLast = (old == gridDim.x - 1);
    }
    __syncthreads();
    if (amLast) {
        float a = 0.f;
        for (int i = threadIdx.x; i < gridDim.x; i += 256) a += g_partial[i];
        sred[threadIdx.x] = a;
        __syncthreads();
        for (int s = 128; s > 0; s >>= 1) {
            if (threadIdx.x < s) sred[threadIdx.x] += sred[threadIdx.x + s];
            __syncthreads();
        }
        if (threadIdx.x == 0) { g_expsum = sred[0]; g_ctr = 0u; }
    }
}

// ---------------- agg body ----------------
__device__ __forceinline__ float4 agg_row(int n, int lane)
{
    float inv = __frcp_rn(g_expsum);
    int beg = g_off[n], end = g_off[n + 1];
    float4 acc = make_float4(0.f, 0.f, 0.f, 0.f);
    int i = beg;
    for (; i + 3 < end; i += 4) {
        int   s0 = g_src[i],   s1 = g_src[i+1], s2 = g_src[i+2], s3 = g_src[i+3];
        float w0 = g_att[i],   w1 = g_att[i+1], w2 = g_att[i+2], w3 = g_att[i+3];
        float4 v0 = *(const float4*)(g_xc + (size_t)s0 * DH + lane * 4);
        float4 v1 = *(const float4*)(g_xc + (size_t)s1 * DH + lane * 4);
        float4 v2 = *(const float4*)(g_xc + (size_t)s2 * DH + lane * 4);
        float4 v3 = *(const float4*)(g_xc + (size_t)s3 * DH + lane * 4);
        acc.x += w0*v0.x + w1*v1.x + w2*v2.x + w3*v3.x;
        acc.y += w0*v0.y + w1*v1.y + w2*v2.y + w3*v3.y;
        acc.z += w0*v0.z + w1*v1.z + w2*v2.z + w3*v3.z;
        acc.w += w0*v0.w + w1*v1.w + w2*v2.w + w3*v3.w;
    }
    for (; i < end; i++) {
        float w = g_att[i];
        float4 v = *(const float4*)(g_xc + (size_t)g_src[i] * DH + lane * 4);
        acc.x += w*v.x; acc.y += w*v.y; acc.z += w*v.z; acc.w += w*v.w;
    }
    float4 o;
    o.x = fmaxf(acc.x * inv, 0.f);
    o.y = fmaxf(acc.y * inv, 0.f);
    o.z = fmaxf(acc.z * inv, 0.f);
    o.w = fmaxf(acc.w * inv, 0.f);
    return o;
}

// ---------------- agg + entqk fused ----------------
__global__ void aggentqk_kernel(float* __restrict__ hout, int rotbase,
                                const float* __restrict__ qW, const float* __restrict__ qb,
                                const float* __restrict__ kW, const float* __restrict__ kb, int N)
{
    int warp = (blockIdx.x * blockDim.x + threadIdx.x) >> 5;
    int lane = threadIdx.x & 31;
    if (warp >= N) return;
    float4 hv = agg_row(warp, lane);
    *(float4*)(hout + (size_t)warp * DH + lane * 4) = hv;
    node_body(hv, warp, lane, rotbase, qW, qb, kW, kb);
}

// ---------------- agg + final path circuit fused ----------------
__global__ void aggfinal_kernel(const float* __restrict__ piW, const float* __restrict__ pib,
                                float* __restrict__ out, int N)
{
    int warp = (blockIdx.x * blockDim.x + threadIdx.x) >> 5;
    int lane = threadIdx.x & 31;
    if (warp >= N) return;
    float4 hv = agg_row(warp, lane);

    float acc[4];
#pragma unroll
    for (int i = 0; i < 4; i++) {
        float4 w = *(const float4*)(piW + i * DH + lane * 4);
        acc[i] = hv.x * w.x + hv.y * w.y + hv.z * w.z + hv.w * w.w;
    }
#pragma unroll
    for (int ofs = 16; ofs >= 1; ofs >>= 1)
#pragma unroll
        for (int i = 0; i < 4; i++) acc[i] += __shfl_xor_sync(FULL, acc[i], ofs);

    float myb0 = 0.f, myb1 = 0.f;
    if (lane < 4) {
        float a = ftanh(acc[lane] + pib[lane]) * (0.5f * PI_HALF);
        float s, c;
        __sincosf(a, &s, &c);
        myb0 = (c - s) * RSQRT2;
        myb1 = (c + s) * RSQRT2;
    }
    float b00 = __shfl_sync(FULL, myb0, 0), b10 = __shfl_sync(FULL, myb1, 0);
    float b01 = __shfl_sync(FULL, myb0, 1), b11 = __shfl_sync(FULL, myb1, 1);
    float b02 = __shfl_sync(FULL, myb0, 2), b12 = __shfl_sync(FULL, myb1, 2);
    float b03 = __shfl_sync(FULL, myb0, 3), b13 = __shfl_sync(FULL, myb1, 3);
    int L = lane & 15;
    float ar = (L & 8 ? b10 : b00) * (L & 4 ? b11 : b01) * (L & 2 ? b12 : b02) * (L & 1 ? b13 : b03);
    float ai = 0.f;
#pragma unroll
    for (int l = 0; l < 3; l++) {
#pragma unroll
        for (int w = 0; w < 4; w++)
            rot_shfl(ar, ai, L, &g_rot[(24 + l * 4 + w) * 8], 8 >> w);
        cnot_shfl(ar, ai, L, 8, 4);
        cnot_shfl(ar, ai, L, 4, 2);
        cnot_shfl(ar, ai, L, 2, 1);
    }
    float z0, z1, z2, z3;
    zexp_shfl(ar, ai, L, z0, z1, z2, z3);
    z0 = __shfl_sync(FULL, z0, 0);
    z1 = __shfl_sync(FULL, z1, 0);
    z2 = __shfl_sync(FULL, z2, 0);
    z3 = __shfl_sync(FULL, z3, 0);
    float4 m = *(const float4*)(g_M + lane * 4);
    out[(size_t)warp * DOUT + lane] = z0 * m.x + z1 * m.y + z2 * m.z + z3 * m.w + g_C[lane];
}

// ---------------- host ----------------
extern "C" void kernel_launch(void* const* d_in, const int* in_sizes, int n_in,
                              void* d_out, int out_size)
{
    const float* x          = (const float*)d_in[0];
    const float* W_in       = (const float*)d_in[1];
    const float* b_in       = (const float*)d_in[2];
    const float* lin_W      = (const float*)d_in[3];
    const float* lin_b      = (const float*)d_in[4];
    const float* qproj_W    = (const float*)d_in[5];
    const float* qproj_b    = (const float*)d_in[6];
    const float* ent_params = (const float*)d_in[7];
    const float* attq_W     = (const float*)d_in[8];
    const float* attq_b     = (const float*)d_in[9];
    const float* attk_W     = (const float*)d_in[10];
    const float* attk_b     = (const float*)d_in[11];
    const float* att_qp     = (const float*)d_in[12];
    const float* path_params= (const float*)d_in[13];
    const float* path_in_W  = (const float*)d_in[14];
    const float* path_in_b  = (const float*)d_in[15];
    const float* path_out_W = (const float*)d_in[16];
    const float* path_out_b = (const float*)d_in[17];
    const float* out_W      = (const float*)d_in[18];
    const float* out_b      = (const float*)d_in[19];
    const int*   edge_index = (const int*)d_in[20];
    float* out = (float*)d_out;

    int N  = in_sizes[0] / DIN;
    int E  = in_sizes[20] / 2;
    int E2 = E + N;

    float *p_h, *p_hn, *p_xc;
    cudaGetSymbolAddress((void**)&p_h,  g_h);
    cudaGetSymbolAddress((void**)&p_hn, g_hn);
    cudaGetSymbolAddress((void**)&p_xc, g_xc);

    int eblocks = (E2 + 255) / 256;
    int nb = (N + 1023) / 1024;   // <= 20; all resident

    setup_kernel<<<(N + 256) / 256, 256>>>(ent_params, att_qp, path_params,
                                           path_out_W, path_out_b, out_W, out_b, N);
    csr_build_kernel<<<nb, 1024>>>(edge_index, E, N, nb);

    // h0 = relu(x @ W_in^T + b_in)
    gemm64<<<(N + 63) / 64, 128>>>(x, W_in, b_in, p_h, N, DIN, 1, nullptr, nullptr);

    // layer 0
    entqk_kernel<<<(N + 7) / 8, 256>>>(p_h, 0, attq_W, attq_b, attk_W, attk_b, N);
    gemm64<<<(N + 63) / 64, 128>>>(p_h, lin_W, lin_b, p_xc, N, DH, 0, qproj_W, qproj_b);
    edge_kernel<<<eblocks, 256>>>(E2, 0);

    // layer 1
    aggentqk_kernel<<<(N + 7) / 8, 256>>>(p_hn, 8,
                                          attq_W + NQ * DH, attq_b + NQ,
                                          attk_W + NQ * DH, attk_b + NQ, N);
    gemm64<<<(N + 63) / 64, 128>>>(p_hn, lin_W + (size_t)DH * DH, lin_b + DH, p_xc, N, DH, 0,
                                   qproj_W + (size_t)DH * NQ, qproj_b + DH);
    edge_kernel<<<eblocks, 256>>>(E2, 1);

    // final
    aggfinal_kernel<<<(N + 7) / 8, 256>>>(path_in_W, path_in_b, out, N);
}

// round 14
// speedup vs baseline: 1.3105x; 1.2371x over previous
#include <cuda_runtime.h>
#include <math.h>

#define NQ 4
#define DH 128
#define DIN 64
#define DOUT 32
#define PI_HALF 1.5707963267948966f
#define RSQRT2 0.7071067811865476f
#define FULL 0xffffffffu

#define MAXN 20000
#define MAXE 300000
#define MAXE2 (MAXN + MAXE)

// ---------------- scratch ----------------
__device__ float g_h[MAXN * DH];
__device__ float g_hn[MAXN * DH];
__device__ float g_xc[MAXN * DH];
__device__ float g_qtrig[MAXN * 8];   // per node: H-folded q amps a0..3 (bit=0), b0..3 (bit=1)
__device__ float g_ktrig[MAXN * 8];   // per node: cos k0..3, sin k0..3
__device__ float g_xq[MAXN * NQ];
__device__ float g_att[MAXE2];        // CSR-ordered exp(score)
__device__ float g_partial[4096];
__device__ float g_expsum;
__device__ unsigned g_ctr;            // last-block ticket (maintained at 0)
__device__ int   g_cnt[MAXN + 1];
__device__ int   g_off[MAXN + 1];
__device__ int   g_cur[MAXN];
__device__ int   g_chain[64];         // scan lookback chain (value = prefix+1; 0 = not ready)
__device__ int   g_src[MAXE2];        // CSR-ordered src node
__device__ int   g_dst[MAXE2];        // CSR-ordered dst node
__device__ float g_rot[36 * 8];       // [0..15] ent, [24..35] path
__device__ float g_attpre[2 * 8];     // per att layer: wZ[4], wX[4]
__device__ float g_M[DOUT * NQ];
__device__ float g_C[DOUT];

__device__ __forceinline__ float ftanh(float x)
{
    x = fmaxf(fminf(x, 15.f), -15.f);
    float t = __expf(2.f * x);
    return __fdividef(t - 1.f, t + 1.f);
}

// ---------------- setup ----------------
__global__ void setup_kernel(const float* __restrict__ ent, const float* __restrict__ attqp,
                             const float* __restrict__ path,
                             const float* __restrict__ poW, const float* __restrict__ pob,
                             const float* __restrict__ oW, const float* __restrict__ ob, int N)
{
    int gi = blockIdx.x * blockDim.x + threadIdx.x;
    if (gi <= N) g_cnt[gi] = 0;
    if (gi < 64) g_chain[gi] = 0;
    if (blockIdx.x != 0) return;
    int t = threadIdx.x;
    if (t < 36) {
        const float* p;
        if (t < 16)      p = ent + t * 3;
        else if (t < 24) p = attqp + (t - 16) * 3;
        else             p = path + (t - 24) * 3;
        float phi = p[0], th = p[1], om = p[2];
        float ct, st, ca, sa, cb, sb;
        sincosf(0.5f * th, &st, &ct);
        sincosf(0.5f * (phi + om), &sa, &ca);
        sincosf(0.5f * (phi - om), &sb, &cb);
        float* r = g_rot + t * 8;
        r[0] =  ct * ca; r[1] = -ct * sa;
        r[2] = -st * cb; r[3] = -st * sb;
        r[4] =  st * cb; r[5] = -st * sb;
        r[6] =  ct * ca; r[7] =  ct * sa;
    }
    // Rot^dag Z Rot = cos(th) Z - sin(th)(cos(phi) X - sin(phi) Y); real state => <Y>=0
    if (t == 40 || t == 41) {
        int l = t - 40;
        float* pre = g_attpre + l * 8;
        for (int i = 0; i < 4; i++) {
            float phi = attqp[l * 12 + i * 3 + 0];
            float th  = attqp[l * 12 + i * 3 + 1];
            float sth, cth;
            sincosf(th, &sth, &cth);
            pre[i]     = 0.25f * cth;
            pre[4 + i] = -0.5f * sth * cosf(phi);
        }
    }
    if (t >= 64 && t < 64 + DOUT) {
        int o = t - 64;
        float m0 = 0, m1 = 0, m2 = 0, m3 = 0, cc = 0;
        for (int j = 0; j < DH; j++) {
            float w = oW[o * DH + j];
            m0 += w * poW[j * NQ + 0];
            m1 += w * poW[j * NQ + 1];
            m2 += w * poW[j * NQ + 2];
            m3 += w * poW[j * NQ + 3];
            cc += w * pob[j];
        }
        g_M[o * NQ + 0] = m0; g_M[o * NQ + 1] = m1;
        g_M[o * NQ + 2] = m2; g_M[o * NQ + 3] = m3;
        g_C[o] = cc + ob[o];
    }
}

// ---------------- CSR build (split kernels, full grids, 1 edge/thread) ----------------
__global__ void count_kernel(const int* __restrict__ ei, int E, int N)
{
    int e = blockIdx.x * blockDim.x + threadIdx.x;
    if (e >= E + N) return;
    int dst = (e < E) ? ei[E + e] : (e - E);
    atomicAdd(&g_cnt[dst], 1);
}

// single-kernel exclusive scan with chained lookback (blocks all resident: nb <= 20)
__global__ void scan_kernel(int N, int nb)
{
    __shared__ int wsum[32];
    __shared__ int sbase;
    int b = blockIdx.x;
    int i = b * 1024 + threadIdx.x;
    int lane = threadIdx.x & 31, wid = threadIdx.x >> 5;
    int v = (i < N) ? g_cnt[i] : 0;
    int s = v;
#pragma unroll
    for (int o = 1; o < 32; o <<= 1) {
        int t = __shfl_up_sync(FULL, s, o);
        if (lane >= o) s += t;
    }
    if (lane == 31) wsum[wid] = s;
    __syncthreads();
    if (wid == 0) {
        int ws = wsum[lane];
#pragma unroll
        for (int o = 1; o < 32; o <<= 1) {
            int t = __shfl_up_sync(FULL, ws, o);
            if (lane >= o) ws += t;
        }
        wsum[lane] = ws;
    }
    __syncthreads();
    int excl = s - v + (wid ? wsum[wid - 1] : 0);
    if (threadIdx.x == 0) {
        int x;
        if (b == 0) x = 1;
        else { while ((x = *(volatile int*)&g_chain[b - 1]) == 0) {} }
        sbase = x - 1;
    }
    __syncthreads();
    int base = sbase;
    if (i < N) { g_off[i] = base + excl; g_cur[i] = base + excl; }
    if (threadIdx.x == 1023) {
        int tot = base + excl + v;
        __threadfence();
        *(volatile int*)&g_chain[b] = tot + 1;
        if (b == nb - 1) g_off[N] = tot;
    }
}

__global__ void fill_kernel(const int* __restrict__ ei, int E, int N)
{
    int e = blockIdx.x * blockDim.x + threadIdx.x;
    if (e >= E + N) return;
    int src = (e < E) ? ei[e]     : (e - E);
    int dst = (e < E) ? ei[E + e] : (e - E);
    int pos = atomicAdd(&g_cur[dst], 1);
    g_src[pos] = src;
    g_dst[pos] = dst;
}

// ---------------- SGEMM 64x128 tile, 128 threads, 8x8 microkernel ----------------
__global__ __launch_bounds__(128)
void gemm64(const float* __restrict__ A, const float* __restrict__ W,
            const float* __restrict__ bias, float* __restrict__ C,
            int M, int K, int doRelu,
            const float* __restrict__ pW, const float* __restrict__ pb)
{
    __shared__ float As[16][64];
    __shared__ float Bs[16][128];
    int tid = threadIdx.x;
    int m0 = blockIdx.x * 64;
    int tx = tid & 15, ty = tid >> 4;

    float acc[8][8];
#pragma unroll
    for (int i = 0; i < 8; i++)
#pragma unroll
        for (int j = 0; j < 8; j++) acc[i][j] = 0.f;

    int ar = tid >> 1;
    int ac = (tid & 1) * 8;
    bool mok = (m0 + ar) < M;
    const float* ap = A + (size_t)(m0 + ar) * K + ac;
    const float* bp = W + (size_t)tid * K;

    float4 pa0, pa1, pb0, pb1, pb2, pb3;
    float4 z4 = make_float4(0.f, 0.f, 0.f, 0.f);
    pa0 = mok ? *(const float4*)(ap)     : z4;
    pa1 = mok ? *(const float4*)(ap + 4) : z4;
    pb0 = *(const float4*)(bp + 0);
    pb1 = *(const float4*)(bp + 4);
    pb2 = *(const float4*)(bp + 8);
    pb3 = *(const float4*)(bp + 12);

    for (int k0 = 0; k0 < K; k0 += 16) {
        __syncthreads();
        As[ac + 0][ar] = pa0.x; As[ac + 1][ar] = pa0.y;
        As[ac + 2][ar] = pa0.z; As[ac + 3][ar] = pa0.w;
        As[ac + 4][ar] = pa1.x; As[ac + 5][ar] = pa1.y;
        As[ac + 6][ar] = pa1.z; As[ac + 7][ar] = pa1.w;
        Bs[ 0][tid] = pb0.x; Bs[ 1][tid] = pb0.y; Bs[ 2][tid] = pb0.z; Bs[ 3][tid] = pb0.w;
        Bs[ 4][tid] = pb1.x; Bs[ 5][tid] = pb1.y; Bs[ 6][tid] = pb1.z; Bs[ 7][tid] = pb1.w;
        Bs[ 8][tid] = pb2.x; Bs[ 9][tid] = pb2.y; Bs[10][tid] = pb2.z; Bs[11][tid] = pb2.w;
        Bs[12][tid] = pb3.x; Bs[13][tid] = pb3.y; Bs[14][tid] = pb3.z; Bs[15][tid] = pb3.w;
        __syncthreads();
        if (k0 + 16 < K) {
            pa0 = mok ? *(const float4*)(ap + k0 + 16)     : z4;
            pa1 = mok ? *(const float4*)(ap + k0 + 16 + 4) : z4;
            pb0 = *(const float4*)(bp + k0 + 16);
            pb1 = *(const float4*)(bp + k0 + 20);
            pb2 = *(const float4*)(bp + k0 + 24);
            pb3 = *(const float4*)(bp + k0 + 28);
        }
#pragma unroll
        for (int kk = 0; kk < 16; kk++) {
            float4 ra0 = *(const float4*)&As[kk][ty * 4];
            float4 ra1 = *(const float4*)&As[kk][32 + ty * 4];
            float4 rb0 = *(const float4*)&Bs[kk][tx * 4];
            float4 rb1 = *(const float4*)&Bs[kk][64 + tx * 4];
            float a[8] = {ra0.x, ra0.y, ra0.z, ra0.w, ra1.x, ra1.y, ra1.z, ra1.w};
            float b[8] = {rb0.x, rb0.y, rb0.z, rb0.w, rb1.x, rb1.y, rb1.z, rb1.w};
#pragma unroll
            for (int i = 0; i < 8; i++)
#pragma unroll
                for (int j = 0; j < 8; j++) acc[i][j] += a[i] * b[j];
        }
    }

    float bb[8], pbv[8];
    float4 wcol[8];
#pragma unroll
    for (int j = 0; j < 8; j++) {
        int n = (j < 4) ? (tx * 4 + j) : (64 + tx * 4 + (j - 4));
        bb[j] = bias[n];
        if (pW) { wcol[j] = *(const float4*)(pW + n * NQ); pbv[j] = pb[n]; }
    }
#pragma unroll
    for (int i = 0; i < 8; i++) {
        int m = m0 + ((i < 4) ? (ty * 4 + i) : (32 + ty * 4 + (i - 4)));
        if (m < M) {
            float4 zz = z4;
            if (pW) zz = *(const float4*)(g_xq + m * NQ);
            float o[8];
#pragma unroll
            for (int j = 0; j < 8; j++) {
                float v = acc[i][j] + bb[j];
                if (pW) v += pbv[j] + zz.x * wcol[j].x + zz.y * wcol[j].y
                            + zz.z * wcol[j].z + zz.w * wcol[j].w;
                if (doRelu) v = fmaxf(v, 0.f);
                o[j] = v;
            }
            *(float4*)(C + (size_t)m * DH + tx * 4)      = make_float4(o[0], o[1], o[2], o[3]);
            *(float4*)(C + (size_t)m * DH + 64 + tx * 4) = make_float4(o[4], o[5], o[6], o[7]);
        }
    }
}

// ---------------- shuffle statevector gates, HALF-WARP version ----------------
// Lane L = lane & 15 holds amplitude index L of its half's node. All xor offsets <= 8
// stay within the 16-lane half, so two nodes ride one warp with zero interaction.
__device__ __forceinline__ void cnot_shfl(float& ar, float& ai, int L, int mc, int mt)
{
    float pr = __shfl_xor_sync(FULL, ar, mt);
    float pi = __shfl_xor_sync(FULL, ai, mt);
    if (L & mc) { ar = pr; ai = pi; }
}

__device__ __forceinline__ void rot_shfl(float& ar, float& ai, int L, const float* __restrict__ u, int m)
{
    float pr = __shfl_xor_sync(FULL, ar, m);
    float pi = __shfl_xor_sync(FULL, ai, m);
    bool low = !(L & m);
    float owr = low ? u[0] : u[6], owi = low ? u[1] : u[7];
    float par = low ? u[2] : u[4], pai = low ? u[3] : u[5];
    float nr = owr * ar - owi * ai + par * pr - pai * pi;
    float ni = owr * ai + owi * ar + par * pi + pai * pr;
    ar = nr; ai = ni;
}

__device__ __forceinline__ void zexp_shfl(float ar, float ai, int L,
                                          float& z0, float& z1, float& z2, float& z3)
{
    float p = ar * ar + ai * ai;
    z0 = (L & 8) ? -p : p;
    z1 = (L & 4) ? -p : p;
    z2 = (L & 2) ? -p : p;
    z3 = (L & 1) ? -p : p;
#pragma unroll
    for (int o = 1; o < 16; o <<= 1) {
        z0 += __shfl_xor_sync(FULL, z0, o);
        z1 += __shfl_xor_sync(FULL, z1, o);
        z2 += __shfl_xor_sync(FULL, z2, o);
        z3 += __shfl_xor_sync(FULL, z3, o);
    }
}

// ---------------- half-warp per-node body: qk matvec + trig + ent circuit ----------------
// ha/hb = this lane's 8 h values (row chunk [hl*8, hl*8+8)); 2 nodes per warp.
__device__ __forceinline__ void node_body_h(float4 ha, float4 hb, int n, int lane, int rotbase,
                                            const float* __restrict__ qW, const float* __restrict__ qb,
                                            const float* __restrict__ kW, const float* __restrict__ kb)
{
    int hl = lane & 15;
    int hsel = lane & 16;    // 0 for low half, 16 for high half
    float acc[8];
#pragma unroll
    for (int i = 0; i < 4; i++) {
        const float* wq = qW + i * DH + hl * 8;
        float4 w0 = *(const float4*)wq, w1 = *(const float4*)(wq + 4);
        acc[i] = ha.x * w0.x + ha.y * w0.y + ha.z * w0.z + ha.w * w0.w
               + hb.x * w1.x + hb.y * w1.y + hb.z * w1.z + hb.w * w1.w;
        const float* wk = kW + i * DH + hl * 8;
        float4 v0 = *(const float4*)wk, v1 = *(const float4*)(wk + 4);
        acc[4 + i] = ha.x * v0.x + ha.y * v0.y + ha.z * v0.z + ha.w * v0.w
                   + hb.x * v1.x + hb.y * v1.y + hb.z * v1.z + hb.w * v1.w;
    }
#pragma unroll
    for (int ofs = 8; ofs >= 1; ofs >>= 1)
#pragma unroll
        for (int i = 0; i < 8; i++) acc[i] += __shfl_xor_sync(FULL, acc[i], ofs);
    if (hl < 8) {
        float b = (hl < 4) ? qb[hl] : kb[hl - 4];
        float half = ftanh(acc[hl] + b) * (0.5f * PI_HALF);
        float s, c;
        __sincosf(half, &s, &c);
        if (hl < 4) {
            g_qtrig[n * 8 + hl]     = (c + s) * RSQRT2;   // bit = 0 (H folded)
            g_qtrig[n * 8 + 4 + hl] = (c - s) * RSQRT2;   // bit = 1
        } else {
            g_ktrig[n * 8 + hl - 4] = c;
            g_ktrig[n * 8 + hl]     = s;
        }
    }
    // ent circuit on each 16-lane half (h[0..3] live in lane hsel's ha)
    float h0 = __shfl_sync(FULL, ha.x, hsel);
    float h1 = __shfl_sync(FULL, ha.y, hsel);
    float h2 = __shfl_sync(FULL, ha.z, hsel);
    float h3 = __shfl_sync(FULL, ha.w, hsel);
    float myc = 1.f, mys = 0.f;
    if (hl < 4) {
        float myh = (hl == 0) ? h0 : (hl == 1) ? h1 : (hl == 2) ? h2 : h3;
        float a = ftanh(myh) * (0.5f * PI_HALF);
        __sincosf(a, &mys, &myc);
    }
    float c0 = __shfl_sync(FULL, myc, hsel | 0), s0 = __shfl_sync(FULL, mys, hsel | 0);
    float c1 = __shfl_sync(FULL, myc, hsel | 1), s1 = __shfl_sync(FULL, mys, hsel | 1);
    float c2 = __shfl_sync(FULL, myc, hsel | 2), s2 = __shfl_sync(FULL, mys, hsel | 2);
    float c3 = __shfl_sync(FULL, myc, hsel | 3), s3 = __shfl_sync(FULL, mys, hsel | 3);
    int L = hl;
    float ar = (L & 8 ? s0 : c0) * (L & 4 ? s1 : c1) * (L & 2 ? s2 : c2) * (L & 1 ? s3 : c3);
    float ai = 0.f;
#pragma unroll
    for (int sub = 0; sub < 2; sub++) {
        cnot_shfl(ar, ai, L, 8, 4);
        cnot_shfl(ar, ai, L, 4, 2);
        cnot_shfl(ar, ai, L, 2, 1);
#pragma unroll
        for (int w = 0; w < 4; w++)
            rot_shfl(ar, ai, L, &g_rot[(rotbase + sub * 4 + w) * 8], 8 >> w);
        cnot_shfl(ar, ai, L, 8, 1);
    }
    float z0, z1, z2, z3;
    zexp_shfl(ar, ai, L, z0, z1, z2, z3);
    if (hl == 0)
        *(float4*)(g_xq + n * NQ) = make_float4(z0, z1, z2, z3);
}

__global__ void entqk_kernel(const float* __restrict__ h, int rotbase,
                             const float* __restrict__ qW, const float* __restrict__ qb,
                             const float* __restrict__ kW, const float* __restrict__ kb, int N)
{
    int gid = blockIdx.x * blockDim.x + threadIdx.x;
    int n = gid >> 4;            // node per 16-lane half
    int lane = threadIdx.x & 31;
    int hl = lane & 15;
    if (n >= N) return;
    const float* hr = h + (size_t)n * DH + hl * 8;
    float4 ha = *(const float4*)hr;
    float4 hb = *(const float4*)(hr + 4);
    node_body_h(ha, hb, n, lane, rotbase, qW, qb, kW, kb);
}

// ---------------- per-edge attention: CSR-slot order, observable-collapsed Rot ----------------
__global__ void edge_kernel(int E2, int layer)
{
    __shared__ float pre[8];
    if (threadIdx.x < 8) pre[threadIdx.x] = g_attpre[layer * 8 + threadIdx.x];
    __syncthreads();

    int e = blockIdx.x * blockDim.x + threadIdx.x;
    float wgt = 0.f;
    if (e < E2) {
        int src = g_src[e];
        int dst = g_dst[e];
        const float4* qp = (const float4*)(g_qtrig + src * 8);
        const float4* kp = (const float4*)(g_ktrig + dst * 8);
        float4 qa = qp[0], qb = qp[1];
        float4 kc = kp[0], ks = kp[1];
        float aa[4] = {qa.x, qa.y, qa.z, qa.w};
        float bb[4] = {qb.x, qb.y, qb.z, qb.w};
        float v[16];
#pragma unroll
        for (int idx = 0; idx < 16; idx++)
            v[idx] = (idx & 8 ? bb[0] : aa[0]) * (idx & 4 ? bb[1] : aa[1]) *
                     (idx & 2 ? bb[2] : aa[2]) * (idx & 1 ? bb[3] : aa[3]);
        float kcc[4] = {kc.x, kc.y, kc.z, kc.w};
        float kss[4] = {ks.x, ks.y, ks.z, ks.w};
#pragma unroll
        for (int i = 0; i < 4; i++) {
            float cs = kcc[i], sc = kss[i];
            int mc = 8 >> i, mt = 8 >> ((i + 1) & 3);
#pragma unroll
            for (int idx = 0; idx < 16; idx++) {
                if ((idx & mc) && !(idx & mt)) {
                    int j = idx | mt;
                    float a = v[idx], b = v[j];
                    v[idx] = cs * a - sc * b;
                    v[j]   = sc * a + cs * b;
                }
            }
        }
        float p[16];
#pragma unroll
        for (int idx = 0; idx < 16; idx++) p[idx] = v[idx] * v[idx];
        float score = 0.f;
#pragma unroll
        for (int i = 0; i < 4; i++) {
            int m = 8 >> i;
            float zs = 0.f, xs = 0.f;
#pragma unroll
            for (int idx = 0; idx < 16; idx++) {
                if (idx & m) zs -= p[idx];
                else { zs += p[idx]; xs += v[idx] * v[idx | m]; }
            }
            score += pre[i] * zs + pre[4 + i] * (2.f * xs);
        }
        wgt = __expf(score);
        g_att[e] = wgt;
    }
    __shared__ float sred[256];
    sred[threadIdx.x] = wgt;
    __syncthreads();
    for (int s = 128; s > 0; s >>= 1) {
        if (threadIdx.x < s) sred[threadIdx.x] += sred[threadIdx.x + s];
        __syncthreads();
    }
    if (threadIdx.x == 0) g_partial[blockIdx.x] = sred[0];

    __shared__ bool amLast;
    __threadfence();
    if (threadIdx.x == 0) {
        unsigned old = atomicAdd(&g_ctr, 1u);
        amLast = (old == gridDim.x - 1);
    }
    __syncthreads();
    if (amLast) {
        float a = 0.f;
        for (int i = threadIdx.x; i < gridDim.x; i += 256) a += g_partial[i];
        sred[threadIdx.x] = a;
        __syncthreads();
        for (int s = 128; s > 0; s >>= 1) {
            if (threadIdx.x < s) sred[threadIdx.x] += sred[threadIdx.x + s];
            __syncthreads();
        }
        if (threadIdx.x == 0) { g_expsum = sred[0]; g_ctr = 0u; }
    }
}

// ---------------- half-warp agg: one node per 16 lanes, 8 floats/lane ----------------
__device__ __forceinline__ void agg_row_h(int n, int hl, float4& o0, float4& o1)
{
    float inv = __frcp_rn(g_expsum);
    int beg = g_off[n], end = g_off[n + 1];
    float4 a0 = make_float4(0.f, 0.f, 0.f, 0.f);
    float4 a1 = make_float4(0.f, 0.f, 0.f, 0.f);
    int i = beg;
    for (; i + 1 < end; i += 2) {
        int   s0 = g_src[i],  s1 = g_src[i + 1];
        float w0 = g_att[i],  w1 = g_att[i + 1];
        const float* r0 = g_xc + (size_t)s0 * DH + hl * 8;
        const float* r1 = g_xc + (size_t)s1 * DH + hl * 8;
        float4 v00 = *(const float4*)r0, v01 = *(const float4*)(r0 + 4);
        float4 v10 = *(const float4*)r1, v11 = *(const float4*)(r1 + 4);
        a0.x += w0 * v00.x + w1 * v10.x; a0.y += w0 * v00.y + w1 * v10.y;
        a0.z += w0 * v00.z + w1 * v10.z; a0.w += w0 * v00.w + w1 * v10.w;
        a1.x += w0 * v01.x + w1 * v11.x; a1.y += w0 * v01.y + w1 * v11.y;
        a1.z += w0 * v01.z + w1 * v11.z; a1.w += w0 * v01.w + w1 * v11.w;
    }
    if (i < end) {
        float w = g_att[i];
        const float* r = g_xc + (size_t)g_src[i] * DH + hl * 8;
        float4 v0 = *(const float4*)r, v1 = *(const float4*)(r + 4);
        a0.x += w * v0.x; a0.y += w * v0.y; a0.z += w * v0.z; a0.w += w * v0.w;
        a1.x += w * v1.x; a1.y += w * v1.y; a1.z += w * v1.z; a1.w += w * v1.w;
    }
    o0.x = fmaxf(a0.x * inv, 0.f); o0.y = fmaxf(a0.y * inv, 0.f);
    o0.z = fmaxf(a0.z * inv, 0.f); o0.w = fmaxf(a0.w * inv, 0.f);
    o1.x = fmaxf(a1.x * inv, 0.f); o1.y = fmaxf(a1.y * inv, 0.f);
    o1.z = fmaxf(a1.z * inv, 0.f); o1.w = fmaxf(a1.w * inv, 0.f);
}

// ---------------- agg + entqk fused (2 nodes/warp) ----------------
__global__ void aggentqk_kernel(float* __restrict__ hout, int rotbase,
                                const float* __restrict__ qW, const float* __restrict__ qb,
                                const float* __restrict__ kW, const float* __restrict__ kb, int N)
{
    int gid = blockIdx.x * blockDim.x + threadIdx.x;
    int n = gid >> 4;
    int lane = threadIdx.x & 31;
    int hl = lane & 15;
    if (n >= N) return;
    float4 o0, o1;
    agg_row_h(n, hl, o0, o1);
    float* hr = hout + (size_t)n * DH + hl * 8;
    *(float4*)hr = o0;
    *(float4*)(hr + 4) = o1;
    node_body_h(o0, o1, n, lane, rotbase, qW, qb, kW, kb);
}

// ---------------- agg + final path circuit fused (2 nodes/warp) ----------------
__global__ void aggfinal_kernel(const float* __restrict__ piW, const float* __restrict__ pib,
                                float* __restrict__ out, int N)
{
    int gid = blockIdx.x * blockDim.x + threadIdx.x;
    int n = gid >> 4;
    int lane = threadIdx.x & 31;
    int hl = lane & 15;
    int hsel = lane & 16;
    if (n >= N) return;
    float4 o0, o1;
    agg_row_h(n, hl, o0, o1);

    float acc[4];
#pragma unroll
    for (int i = 0; i < 4; i++) {
        const float* w = piW + i * DH + hl * 8;
        float4 w0 = *(const float4*)w, w1 = *(const float4*)(w + 4);
        acc[i] = o0.x * w0.x + o0.y * w0.y + o0.z * w0.z + o0.w * w0.w
               + o1.x * w1.x + o1.y * w1.y + o1.z * w1.z + o1.w * w1.w;
    }
#pragma unroll
    for (int ofs = 8; ofs >= 1; ofs >>= 1)
#pragma unroll
        for (int i = 0; i < 4; i++) acc[i] += __shfl_xor_sync(FULL, acc[i], ofs);

    float myb0 = 0.f, myb1 = 0.f;
    if (hl < 4) {
        float a = ftanh(acc[hl] + pib[hl]) * (0.5f * PI_HALF);
        float s, c;
        __sincosf(a, &s, &c);
        myb0 = (c - s) * RSQRT2;
        myb1 = (c + s) * RSQRT2;
    }
    float b00 = __shfl_sync(FULL, myb0, hsel | 0), b10 = __shfl_sync(FULL, myb1, hsel | 0);
    float b01 = __shfl_sync(FULL, myb0, hsel | 1), b11 = __shfl_sync(FULL, myb1, hsel | 1);
    float b02 = __shfl_sync(FULL, myb0, hsel | 2), b12 = __shfl_sync(FULL, myb1, hsel | 2);
    float b03 = __shfl_sync(FULL, myb0, hsel | 3), b13 = __shfl_sync(FULL, myb1, hsel | 3);
    int L = hl;
    float ar = (L & 8 ? b10 : b00) * (L & 4 ? b11 : b01) * (L & 2 ? b12 : b02) * (L & 1 ? b13 : b03);
    float ai = 0.f;
#pragma unroll
    for (int l = 0; l < 3; l++) {
#pragma unroll
        for (int w = 0; w < 4; w++)
            rot_shfl(ar, ai, L, &g_rot[(24 + l * 4 + w) * 8], 8 >> w);
        cnot_shfl(ar, ai, L, 8, 4);
        cnot_shfl(ar, ai, L, 4, 2);
        cnot_shfl(ar, ai, L, 2, 1);
    }
    float z0, z1, z2, z3;
    zexp_shfl(ar, ai, L, z0, z1, z2, z3);
    // all 16 lanes of the half hold the full sums; each lane writes 2 outputs
    float4 m0 = *(const float4*)(g_M + hl * 4);
    float4 m1 = *(const float4*)(g_M + (hl + 16) * 4);
    out[(size_t)n * DOUT + hl]      = z0 * m0.x + z1 * m0.y + z2 * m0.z + z3 * m0.w + g_C[hl];
    out[(size_t)n * DOUT + hl + 16] = z0 * m1.x + z1 * m1.y + z2 * m1.z + z3 * m1.w + g_C[hl + 16];
}

// ---------------- host ----------------
extern "C" void kernel_launch(void* const* d_in, const int* in_sizes, int n_in,
                              void* d_out, int out_size)
{
    const float* x          = (const float*)d_in[0];
    const float* W_in       = (const float*)d_in[1];
    const float* b_in       = (const float*)d_in[2];
    const float* lin_W      = (const float*)d_in[3];
    const float* lin_b      = (const float*)d_in[4];
    const float* qproj_W    = (const float*)d_in[5];
    const float* qproj_b    = (const float*)d_in[6];
    const float* ent_params = (const float*)d_in[7];
    const float* attq_W     = (const float*)d_in[8];
    const float* attq_b     = (const float*)d_in[9];
    const float* attk_W     = (const float*)d_in[10];
    const float* attk_b     = (const float*)d_in[11];
    const float* att_qp     = (const float*)d_in[12];
    const float* path_params= (const float*)d_in[13];
    const float* path_in_W  = (const float*)d_in[14];
    const float* path_in_b  = (const float*)d_in[15];
    const float* path_out_W = (const float*)d_in[16];
    const float* path_out_b = (const float*)d_in[17];
    const float* out_W      = (const float*)d_in[18];
    const float* out_b      = (const float*)d_in[19];
    const int*   edge_index = (const int*)d_in[20];
    float* out = (float*)d_out;

    int N  = in_sizes[0] / DIN;
    int E  = in_sizes[20] / 2;
    int E2 = E + N;

    float *p_h, *p_hn, *p_xc;
    cudaGetSymbolAddress((void**)&p_h,  g_h);
    cudaGetSymbolAddress((void**)&p_hn, g_hn);
    cudaGetSymbolAddress((void**)&p_xc, g_xc);

    int eblocks = (E2 + 255) / 256;
    int sblocks = (N + 1023) / 1024;
    int nblocks = (N + 15) / 16;       // 16 nodes per 256-thread block (2 per warp)

    setup_kernel<<<(N + 256) / 256, 256>>>(ent_params, att_qp, path_params,
                                           path_out_W, path_out_b, out_W, out_b, N);
    count_kernel<<<eblocks, 256>>>(edge_index, E, N);
    scan_kernel<<<sblocks, 1024>>>(N, sblocks);
    fill_kernel<<<eblocks, 256>>>(edge_index, E, N);

    // h0 = relu(x @ W_in^T + b_in)
    gemm64<<<(N + 63) / 64, 128>>>(x, W_in, b_in, p_h, N, DIN, 1, nullptr, nullptr);

    // layer 0
    entqk_kernel<<<nblocks, 256>>>(p_h, 0, attq_W, attq_b, attk_W, attk_b, N);
    gemm64<<<(N + 63) / 64, 128>>>(p_h, lin_W, lin_b, p_xc, N, DH, 0, qproj_W, qproj_b);
    edge_kernel<<<eblocks, 256>>>(E2, 0);

    // layer 1
    aggentqk_kernel<<<nblocks, 256>>>(p_hn, 8,
                                      attq_W + NQ * DH, attq_b + NQ,
                                      attk_W + NQ * DH, attk_b + NQ, N);
    gemm64<<<(N + 63) / 64, 128>>>(p_hn, lin_W + (size_t)DH * DH, lin_b + DH, p_xc, N, DH, 0,
                                   qproj_W + (size_t)DH * NQ, qproj_b + DH);
    edge_kernel<<<eblocks, 256>>>(E2, 1);

    // final
    aggfinal_kernel<<<nblocks, 256>>>(path_in_W, path_in_b, out, N);
}

// round 15
// speedup vs baseline: 1.3227x; 1.0093x over previous
#include <cuda_runtime.h>
#include <math.h>

#define NQ 4
#define DH 128
#define DIN 64
#define DOUT 32
#define PI_HALF 1.5707963267948966f
#define RSQRT2 0.7071067811865476f
#define FULL 0xffffffffu

#define MAXN 20000
#define MAXE 300000
#define MAXE2 (MAXN + MAXE)

// ---------------- scratch (zero-initialized at module load) ----------------
__device__ float g_h[MAXN * DH];
__device__ float g_hn[MAXN * DH];
__device__ float g_xc[MAXN * DH];
__device__ float g_qtrig[MAXN * 8];   // per node: H-folded q amps a0..3 (bit=0), b0..3 (bit=1)
__device__ float g_ktrig[MAXN * 8];   // per node: cos k0..3, sin k0..3
__device__ float g_xq[MAXN * NQ];
__device__ float g_att[MAXE2];        // CSR-ordered exp(score)
__device__ float g_partial[4096];
__device__ float g_expsum;
__device__ unsigned g_ctr;            // last-block ticket (self-resetting)
__device__ int   g_cnt[MAXN + 1];     // zero at start of every run (module init / aggfinal restore)
__device__ int   g_off[MAXN + 1];
__device__ int   g_cur[MAXN];
__device__ int   g_chain[64];         // scan lookback chain (zeroed by fill for next run)
__device__ int2  g_edge[MAXE2];       // CSR-ordered (src, dst)
__device__ float g_rot[36 * 8];       // [0..15] ent, [24..35] path
__device__ float g_attpre[2 * 8];     // per att layer: wZ[4], wX[4]
__device__ float g_M[DOUT * NQ];
__device__ float g_C[DOUT];

__device__ __forceinline__ float ftanh(float x)
{
    x = fmaxf(fminf(x, 15.f), -15.f);
    float t = __expf(2.f * x);
    return __fdividef(t - 1.f, t + 1.f);
}

// ---------------- count + setup fused (g_cnt pre-zeroed invariantly) ----------------
__global__ void count_setup_kernel(const int* __restrict__ ei, int E, int N,
                                   const float* __restrict__ ent, const float* __restrict__ attqp,
                                   const float* __restrict__ path,
                                   const float* __restrict__ poW, const float* __restrict__ pob,
                                   const float* __restrict__ oW, const float* __restrict__ ob)
{
    int e = blockIdx.x * blockDim.x + threadIdx.x;
    if (e < E + N) {
        int dst = (e < E) ? ei[E + e] : (e - E);
        atomicAdd(&g_cnt[dst], 1);
    }
    if (blockIdx.x != 0) return;
    int t = threadIdx.x;
    if (t < 36) {
        const float* p;
        if (t < 16)      p = ent + t * 3;
        else if (t < 24) p = attqp + (t - 16) * 3;
        else             p = path + (t - 24) * 3;
        float phi = p[0], th = p[1], om = p[2];
        float ct, st, ca, sa, cb, sb;
        sincosf(0.5f * th, &st, &ct);
        sincosf(0.5f * (phi + om), &sa, &ca);
        sincosf(0.5f * (phi - om), &sb, &cb);
        float* r = g_rot + t * 8;
        r[0] =  ct * ca; r[1] = -ct * sa;
        r[2] = -st * cb; r[3] = -st * sb;
        r[4] =  st * cb; r[5] = -st * sb;
        r[6] =  ct * ca; r[7] =  ct * sa;
    }
    // Rot^dag Z Rot = cos(th) Z - sin(th)(cos(phi) X - sin(phi) Y); real state => <Y>=0
    if (t == 40 || t == 41) {
        int l = t - 40;
        float* pre = g_attpre + l * 8;
        for (int i = 0; i < 4; i++) {
            float phi = attqp[l * 12 + i * 3 + 0];
            float th  = attqp[l * 12 + i * 3 + 1];
            float sth, cth;
            sincosf(th, &sth, &cth);
            pre[i]     = 0.25f * cth;
            pre[4 + i] = -0.5f * sth * cosf(phi);
        }
    }
    if (t >= 64 && t < 64 + DOUT) {
        int o = t - 64;
        float m0 = 0, m1 = 0, m2 = 0, m3 = 0, cc = 0;
        for (int j = 0; j < DH; j++) {
            float w = oW[o * DH + j];
            m0 += w * poW[j * NQ + 0];
            m1 += w * poW[j * NQ + 1];
            m2 += w * poW[j * NQ + 2];
            m3 += w * poW[j * NQ + 3];
            cc += w * pob[j];
        }
        g_M[o * NQ + 0] = m0; g_M[o * NQ + 1] = m1;
        g_M[o * NQ + 2] = m2; g_M[o * NQ + 3] = m3;
        g_C[o] = cc + ob[o];
    }
}

// single-kernel exclusive scan with chained lookback (blocks all resident: nb <= 20)
__global__ void scan_kernel(int N, int nb)
{
    __shared__ int wsum[32];
    __shared__ int sbase;
    int b = blockIdx.x;
    int i = b * 1024 + threadIdx.x;
    int lane = threadIdx.x & 31, wid = threadIdx.x >> 5;
    int v = (i < N) ? g_cnt[i] : 0;
    int s = v;
#pragma unroll
    for (int o = 1; o < 32; o <<= 1) {
        int t = __shfl_up_sync(FULL, s, o);
        if (lane >= o) s += t;
    }
    if (lane == 31) wsum[wid] = s;
    __syncthreads();
    if (wid == 0) {
        int ws = wsum[lane];
#pragma unroll
        for (int o = 1; o < 32; o <<= 1) {
            int t = __shfl_up_sync(FULL, ws, o);
            if (lane >= o) ws += t;
        }
        wsum[lane] = ws;
    }
    __syncthreads();
    int excl = s - v + (wid ? wsum[wid - 1] : 0);
    if (threadIdx.x == 0) {
        int x;
        if (b == 0) x = 1;
        else { while ((x = *(volatile int*)&g_chain[b - 1]) == 0) {} }
        sbase = x - 1;
    }
    __syncthreads();
    int base = sbase;
    if (i < N) { g_off[i] = base + excl; g_cur[i] = base + excl; }
    if (threadIdx.x == 1023) {
        int tot = base + excl + v;
        __threadfence();
        *(volatile int*)&g_chain[b] = tot + 1;
        if (b == nb - 1) g_off[N] = tot;
    }
}

__global__ void fill_kernel(const int* __restrict__ ei, int E, int N)
{
    int e = blockIdx.x * blockDim.x + threadIdx.x;
    if (e < E + N) {
        int src = (e < E) ? ei[e]     : (e - E);
        int dst = (e < E) ? ei[E + e] : (e - E);
        int pos = atomicAdd(&g_cur[dst], 1);
        g_edge[pos] = make_int2(src, dst);
    }
    // restore scan chain for next graph replay (scan completed before this kernel)
    if (blockIdx.x == 0 && threadIdx.x < 64) g_chain[threadIdx.x] = 0;
}

// ---------------- SGEMM 64x128 tile, 128 threads, 8x8 microkernel ----------------
__global__ __launch_bounds__(128)
void gemm64(const float* __restrict__ A, const float* __restrict__ W,
            const float* __restrict__ bias, float* __restrict__ C,
            int M, int K, int doRelu,
            const float* __restrict__ pW, const float* __restrict__ pb)
{
    __shared__ float As[16][64];
    __shared__ float Bs[16][128];
    int tid = threadIdx.x;
    int m0 = blockIdx.x * 64;
    int tx = tid & 15, ty = tid >> 4;

    float acc[8][8];
#pragma unroll
    for (int i = 0; i < 8; i++)
#pragma unroll
        for (int j = 0; j < 8; j++) acc[i][j] = 0.f;

    int ar = tid >> 1;
    int ac = (tid & 1) * 8;
    bool mok = (m0 + ar) < M;
    const float* ap = A + (size_t)(m0 + ar) * K + ac;
    const float* bp = W + (size_t)tid * K;

    float4 pa0, pa1, pb0, pb1, pb2, pb3;
    float4 z4 = make_float4(0.f, 0.f, 0.f, 0.f);
    pa0 = mok ? *(const float4*)(ap)     : z4;
    pa1 = mok ? *(const float4*)(ap + 4) : z4;
    pb0 = *(const float4*)(bp + 0);
    pb1 = *(const float4*)(bp + 4);
    pb2 = *(const float4*)(bp + 8);
    pb3 = *(const float4*)(bp + 12);

    for (int k0 = 0; k0 < K; k0 += 16) {
        __syncthreads();
        As[ac + 0][ar] = pa0.x; As[ac + 1][ar] = pa0.y;
        As[ac + 2][ar] = pa0.z; As[ac + 3][ar] = pa0.w;
        As[ac + 4][ar] = pa1.x; As[ac + 5][ar] = pa1.y;
        As[ac + 6][ar] = pa1.z; As[ac + 7][ar] = pa1.w;
        Bs[ 0][tid] = pb0.x; Bs[ 1][tid] = pb0.y; Bs[ 2][tid] = pb0.z; Bs[ 3][tid] = pb0.w;
        Bs[ 4][tid] = pb1.x; Bs[ 5][tid] = pb1.y; Bs[ 6][tid] = pb1.z; Bs[ 7][tid] = pb1.w;
        Bs[ 8][tid] = pb2.x; Bs[ 9][tid] = pb2.y; Bs[10][tid] = pb2.z; Bs[11][tid] = pb2.w;
        Bs[12][tid] = pb3.x; Bs[13][tid] = pb3.y; Bs[14][tid] = pb3.z; Bs[15][tid] = pb3.w;
        __syncthreads();
        if (k0 + 16 < K) {
            pa0 = mok ? *(const float4*)(ap + k0 + 16)     : z4;
            pa1 = mok ? *(const float4*)(ap + k0 + 16 + 4) : z4;
            pb0 = *(const float4*)(bp + k0 + 16);
            pb1 = *(const float4*)(bp + k0 + 20);
            pb2 = *(const float4*)(bp + k0 + 24);
            pb3 = *(const float4*)(bp + k0 + 28);
        }
#pragma unroll
        for (int kk = 0; kk < 16; kk++) {
            float4 ra0 = *(const float4*)&As[kk][ty * 4];
            float4 ra1 = *(const float4*)&As[kk][32 + ty * 4];
            float4 rb0 = *(const float4*)&Bs[kk][tx * 4];
            float4 rb1 = *(const float4*)&Bs[kk][64 + tx * 4];
            float a[8] = {ra0.x, ra0.y, ra0.z, ra0.w, ra1.x, ra1.y, ra1.z, ra1.w};
            float b[8] = {rb0.x, rb0.y, rb0.z, rb0.w, rb1.x, rb1.y, rb1.z, rb1.w};
#pragma unroll
            for (int i = 0; i < 8; i++)
#pragma unroll
                for (int j = 0; j < 8; j++) acc[i][j] += a[i] * b[j];
        }
    }

    float bb[8], pbv[8];
    float4 wcol[8];
#pragma unroll
    for (int j = 0; j < 8; j++) {
        int n = (j < 4) ? (tx * 4 + j) : (64 + tx * 4 + (j - 4));
        bb[j] = bias[n];
        if (pW) { wcol[j] = *(const float4*)(pW + n * NQ); pbv[j] = pb[n]; }
    }
#pragma unroll
    for (int i = 0; i < 8; i++) {
        int m = m0 + ((i < 4) ? (ty * 4 + i) : (32 + ty * 4 + (i - 4)));
        if (m < M) {
            float4 zz = z4;
            if (pW) zz = *(const float4*)(g_xq + m * NQ);
            float o[8];
#pragma unroll
            for (int j = 0; j < 8; j++) {
                float v = acc[i][j] + bb[j];
                if (pW) v += pbv[j] + zz.x * wcol[j].x + zz.y * wcol[j].y
                            + zz.z * wcol[j].z + zz.w * wcol[j].w;
                if (doRelu) v = fmaxf(v, 0.f);
                o[j] = v;
            }
            *(float4*)(C + (size_t)m * DH + tx * 4)      = make_float4(o[0], o[1], o[2], o[3]);
            *(float4*)(C + (size_t)m * DH + 64 + tx * 4) = make_float4(o[4], o[5], o[6], o[7]);
        }
    }
}

// ---------------- shuffle statevector gates, half-warp (2 nodes/warp) ----------------
__device__ __forceinline__ void cnot_shfl(float& ar, float& ai, int L, int mc, int mt)
{
    float pr = __shfl_xor_sync(FULL, ar, mt);
    float pi = __shfl_xor_sync(FULL, ai, mt);
    if (L & mc) { ar = pr; ai = pi; }
}

__device__ __forceinline__ void rot_shfl(float& ar, float& ai, int L, const float* __restrict__ u, int m)
{
    float pr = __shfl_xor_sync(FULL, ar, m);
    float pi = __shfl_xor_sync(FULL, ai, m);
    bool low = !(L & m);
    float owr = low ? u[0] : u[6], owi = low ? u[1] : u[7];
    float par = low ? u[2] : u[4], pai = low ? u[3] : u[5];
    float nr = owr * ar - owi * ai + par * pr - pai * pi;
    float ni = owr * ai + owi * ar + par * pi + pai * pr;
    ar = nr; ai = ni;
}

__device__ __forceinline__ void zexp_shfl(float ar, float ai, int L,
                                          float& z0, float& z1, float& z2, float& z3)
{
    float p = ar * ar + ai * ai;
    z0 = (L & 8) ? -p : p;
    z1 = (L & 4) ? -p : p;
    z2 = (L & 2) ? -p : p;
    z3 = (L & 1) ? -p : p;
#pragma unroll
    for (int o = 1; o < 16; o <<= 1) {
        z0 += __shfl_xor_sync(FULL, z0, o);
        z1 += __shfl_xor_sync(FULL, z1, o);
        z2 += __shfl_xor_sync(FULL, z2, o);
        z3 += __shfl_xor_sync(FULL, z3, o);
    }
}

// ---------------- half-warp per-node body: qk matvec + trig + ent circuit ----------------
__device__ __forceinline__ void node_body_h(float4 ha, float4 hb, int n, int lane, int rotbase,
                                            const float* __restrict__ qW, const float* __restrict__ qb,
                                            const float* __restrict__ kW, const float* __restrict__ kb)
{
    int hl = lane & 15;
    int hsel = lane & 16;
    float acc[8];
#pragma unroll
    for (int i = 0; i < 4; i++) {
        const float* wq = qW + i * DH + hl * 8;
        float4 w0 = *(const float4*)wq, w1 = *(const float4*)(wq + 4);
        acc[i] = ha.x * w0.x + ha.y * w0.y + ha.z * w0.z + ha.w * w0.w
               + hb.x * w1.x + hb.y * w1.y + hb.z * w1.z + hb.w * w1.w;
        const float* wk = kW + i * DH + hl * 8;
        float4 v0 = *(const float4*)wk, v1 = *(const float4*)(wk + 4);
        acc[4 + i] = ha.x * v0.x + ha.y * v0.y + ha.z * v0.z + ha.w * v0.w
                   + hb.x * v1.x + hb.y * v1.y + hb.z * v1.z + hb.w * v1.w;
    }
#pragma unroll
    for (int ofs = 8; ofs >= 1; ofs >>= 1)
#pragma unroll
        for (int i = 0; i < 8; i++) acc[i] += __shfl_xor_sync(FULL, acc[i], ofs);
    if (hl < 8) {
        float b = (hl < 4) ? qb[hl] : kb[hl - 4];
        float half = ftanh(acc[hl] + b) * (0.5f * PI_HALF);
        float s, c;
        __sincosf(half, &s, &c);
        if (hl < 4) {
            g_qtrig[n * 8 + hl]     = (c + s) * RSQRT2;   // bit = 0 (H folded)
            g_qtrig[n * 8 + 4 + hl] = (c - s) * RSQRT2;   // bit = 1
        } else {
            g_ktrig[n * 8 + hl - 4] = c;
            g_ktrig[n * 8 + hl]     = s;
        }
    }
    float h0 = __shfl_sync(FULL, ha.x, hsel);
    float h1 = __shfl_sync(FULL, ha.y, hsel);
    float h2 = __shfl_sync(FULL, ha.z, hsel);
    float h3 = __shfl_sync(FULL, ha.w, hsel);
    float myc = 1.f, mys = 0.f;
    if (hl < 4) {
        float myh = (hl == 0) ? h0 : (hl == 1) ? h1 : (hl == 2) ? h2 : h3;
        float a = ftanh(myh) * (0.5f * PI_HALF);
        __sincosf(a, &mys, &myc);
    }
    float c0 = __shfl_sync(FULL, myc, hsel | 0), s0 = __shfl_sync(FULL, mys, hsel | 0);
    float c1 = __shfl_sync(FULL, myc, hsel | 1), s1 = __shfl_sync(FULL, mys, hsel | 1);
    float c2 = __shfl_sync(FULL, myc, hsel | 2), s2 = __shfl_sync(FULL, mys, hsel | 2);
    float c3 = __shfl_sync(FULL, myc, hsel | 3), s3 = __shfl_sync(FULL, mys, hsel | 3);
    int L = hl;
    float ar = (L & 8 ? s0 : c0) * (L & 4 ? s1 : c1) * (L & 2 ? s2 : c2) * (L & 1 ? s3 : c3);
    float ai = 0.f;
#pragma unroll
    for (int sub = 0; sub < 2; sub++) {
        cnot_shfl(ar, ai, L, 8, 4);
        cnot_shfl(ar, ai, L, 4, 2);
        cnot_shfl(ar, ai, L, 2, 1);
#pragma unroll
        for (int w = 0; w < 4; w++)
            rot_shfl(ar, ai, L, &g_rot[(rotbase + sub * 4 + w) * 8], 8 >> w);
        cnot_shfl(ar, ai, L, 8, 1);
    }
    float z0, z1, z2, z3;
    zexp_shfl(ar, ai, L, z0, z1, z2, z3);
    if (hl == 0)
        *(float4*)(g_xq + n * NQ) = make_float4(z0, z1, z2, z3);
}

__global__ void entqk_kernel(const float* __restrict__ h, int rotbase,
                             const float* __restrict__ qW, const float* __restrict__ qb,
                             const float* __restrict__ kW, const float* __restrict__ kb, int N)
{
    int gid = blockIdx.x * blockDim.x + threadIdx.x;
    int n = gid >> 4;
    int lane = threadIdx.x & 31;
    int hl = lane & 15;
    if (n >= N) return;
    const float* hr = h + (size_t)n * DH + hl * 8;
    float4 ha = *(const float4*)hr;
    float4 hb = *(const float4*)(hr + 4);
    node_body_h(ha, hb, n, lane, rotbase, qW, qb, kW, kb);
}

// ---------------- per-edge attention: CSR-slot order, observable-collapsed Rot ----------------
__global__ void edge_kernel(int E2, int layer)
{
    __shared__ float pre[8];
    if (threadIdx.x < 8) pre[threadIdx.x] = g_attpre[layer * 8 + threadIdx.x];
    __syncthreads();

    int e = blockIdx.x * blockDim.x + threadIdx.x;
    float wgt = 0.f;
    if (e < E2) {
        int2 ed = g_edge[e];
        const float4* qp = (const float4*)(g_qtrig + ed.x * 8);
        const float4* kp = (const float4*)(g_ktrig + ed.y * 8);
        float4 qa = qp[0], qb = qp[1];
        float4 kc = kp[0], ks = kp[1];
        float aa[4] = {qa.x, qa.y, qa.z, qa.w};
        float bb[4] = {qb.x, qb.y, qb.z, qb.w};
        float v[16];
#pragma unroll
        for (int idx = 0; idx < 16; idx++)
            v[idx] = (idx & 8 ? bb[0] : aa[0]) * (idx & 4 ? bb[1] : aa[1]) *
                     (idx & 2 ? bb[2] : aa[2]) * (idx & 1 ? bb[3] : aa[3]);
        float kcc[4] = {kc.x, kc.y, kc.z, kc.w};
        float kss[4] = {ks.x, ks.y, ks.z, ks.w};
#pragma unroll
        for (int i = 0; i < 4; i++) {
            float cs = kcc[i], sc = kss[i];
            int mc = 8 >> i, mt = 8 >> ((i + 1) & 3);
#pragma unroll
            for (int idx = 0; idx < 16; idx++) {
                if ((idx & mc) && !(idx & mt)) {
                    int j = idx | mt;
                    float a = v[idx], b = v[j];
                    v[idx] = cs * a - sc * b;
                    v[j]   = sc * a + cs * b;
                }
            }
        }
        float p[16];
#pragma unroll
        for (int idx = 0; idx < 16; idx++) p[idx] = v[idx] * v[idx];
        float score = 0.f;
#pragma unroll
        for (int i = 0; i < 4; i++) {
            int m = 8 >> i;
            float zs = 0.f, xs = 0.f;
#pragma unroll
            for (int idx = 0; idx < 16; idx++) {
                if (idx & m) zs -= p[idx];
                else { zs += p[idx]; xs += v[idx] * v[idx | m]; }
            }
            score += pre[i] * zs + pre[4 + i] * (2.f * xs);
        }
        wgt = __expf(score);
        g_att[e] = wgt;
    }
    __shared__ float sred[256];
    sred[threadIdx.x] = wgt;
    __syncthreads();
    for (int s = 128; s > 0; s >>= 1) {
        if (threadIdx.x < s) sred[threadIdx.x] += sred[threadIdx.x + s];
        __syncthreads();
    }
    if (threadIdx.x == 0) g_partial[blockIdx.x] = sred[0];

    __shared__ bool amLast;
    __threadfence();
    if (threadIdx.x == 0) {
        unsigned old = atomicAdd(&g_ctr, 1u);
        amLast = (old == gridDim.x - 1);
    }
    __syncthreads();
    if (amLast) {
        float a = 0.f;
        for (int i = threadIdx.x; i < gridDim.x; i += 256) a += g_partial[i];
        sred[threadIdx.x] = a;
        __syncthreads();
        for (int s = 128; s > 0; s >>= 1) {
            if (threadIdx.x < s) sred[threadIdx.x] += sred[threadIdx.x + s];
            __syncthreads();
        }
        if (threadIdx.x == 0) { g_expsum = sred[0]; g_ctr = 0u; }
    }
}

// ---------------- half-warp agg: one node per 16 lanes, 8 floats/lane ----------------
__device__ __forceinline__ void agg_row_h(int n, int hl, float4& o0, float4& o1)
{
    float inv = __frcp_rn(g_expsum);
    int beg = g_off[n], end = g_off[n + 1];
    float4 a0 = make_float4(0.f, 0.f, 0.f, 0.f);
    float4 a1 = make_float4(0.f, 0.f, 0.f, 0.f);
    int i = beg;
    for (; i + 1 < end; i += 2) {
        int   s0 = g_edge[i].x, s1 = g_edge[i + 1].x;
        float w0 = g_att[i],    w1 = g_att[i + 1];
        const float* r0 = g_xc + (size_t)s0 * DH + hl * 8;
        const float* r1 = g_xc + (size_t)s1 * DH + hl * 8;
        float4 v00 = *(const float4*)r0, v01 = *(const float4*)(r0 + 4);
        float4 v10 = *(const float4*)r1, v11 = *(const float4*)(r1 + 4);
        a0.x += w0 * v00.x + w1 * v10.x; a0.y += w0 * v00.y + w1 * v10.y;
        a0.z += w0 * v00.z + w1 * v10.z; a0.w += w0 * v00.w + w1 * v10.w;
        a1.x += w0 * v01.x + w1 * v11.x; a1.y += w0 * v01.y + w1 * v11.y;
        a1.z += w0 * v01.z + w1 * v11.z; a1.w += w0 * v01.w + w1 * v11.w;
    }
    if (i < end) {
        float w = g_att[i];
        const float* r = g_xc + (size_t)g_edge[i].x * DH + hl * 8;
        float4 v0 = *(const float4*)r, v1 = *(const float4*)(r + 4);
        a0.x += w * v0.x; a0.y += w * v0.y; a0.z += w * v0.z; a0.w += w * v0.w;
        a1.x += w * v1.x; a1.y += w * v1.y; a1.z += w * v1.z; a1.w += w * v1.w;
    }
    o0.x = fmaxf(a0.x * inv, 0.f); o0.y = fmaxf(a0.y * inv, 0.f);
    o0.z = fmaxf(a0.z * inv, 0.f); o0.w = fmaxf(a0.w * inv, 0.f);
    o1.x = fmaxf(a1.x * inv, 0.f); o1.y = fmaxf(a1.y * inv, 0.f);
    o1.z = fmaxf(a1.z * inv, 0.f); o1.w = fmaxf(a1.w * inv, 0.f);
}

// ---------------- agg + entqk fused (2 nodes/warp) ----------------
__global__ void aggentqk_kernel(float* __restrict__ hout, int rotbase,
                                const float* __restrict__ qW, const float* __restrict__ qb,
                                const float* __restrict__ kW, const float* __restrict__ kb, int N)
{
    int gid = blockIdx.x * blockDim.x + threadIdx.x;
    int n = gid >> 4;
    int lane = threadIdx.x & 31;
    int hl = lane & 15;
    if (n >= N) return;
    float4 o0, o1;
    agg_row_h(n, hl, o0, o1);
    float* hr = hout + (size_t)n * DH + hl * 8;
    *(float4*)hr = o0;
    *(float4*)(hr + 4) = o1;
    node_body_h(o0, o1, n, lane, rotbase, qW, qb, kW, kb);
}

// ---------------- agg + final path circuit fused (2 nodes/warp) + g_cnt restore ----------------
__global__ void aggfinal_kernel(const float* __restrict__ piW, const float* __restrict__ pib,
                                float* __restrict__ out, int N)
{
    int gid = blockIdx.x * blockDim.x + threadIdx.x;
    // restore g_cnt for the next graph replay (scan consumed it earlier this run)
    if (gid <= N) g_cnt[gid] = 0;
    int n = gid >> 4;
    int lane = threadIdx.x & 31;
    int hl = lane & 15;
    int hsel = lane & 16;
    if (n >= N) return;
    float4 o0, o1;
    agg_row_h(n, hl, o0, o1);

    float acc[4];
#pragma unroll
    for (int i = 0; i < 4; i++) {
        const float* w = piW + i * DH + hl * 8;
        float4 w0 = *(const float4*)w, w1 = *(const float4*)(w + 4);
        acc[i] = o0.x * w0.x + o0.y * w0.y + o0.z * w0.z + o0.w * w0.w
               + o1.x * w1.x + o1.y * w1.y + o1.z * w1.z + o1.w * w1.w;
    }
#pragma unroll
    for (int ofs = 8; ofs >= 1; ofs >>= 1)
#pragma unroll
        for (int i = 0; i < 4; i++) acc[i] += __shfl_xor_sync(FULL, acc[i], ofs);

    float myb0 = 0.f, myb1 = 0.f;
    if (hl < 4) {
        float a = ftanh(acc[hl] + pib[hl]) * (0.5f * PI_HALF);
        float s, c;
        __sincosf(a, &s, &c);
        myb0 = (c - s) * RSQRT2;
        myb1 = (c + s) * RSQRT2;
    }
    float b00 = __shfl_sync(FULL, myb0, hsel | 0), b10 = __shfl_sync(FULL, myb1, hsel | 0);
    float b01 = __shfl_sync(FULL, myb0, hsel | 1), b11 = __shfl_sync(FULL, myb1, hsel | 1);
    float b02 = __shfl_sync(FULL, myb0, hsel | 2), b12 = __shfl_sync(FULL, myb1, hsel | 2);
    float b03 = __shfl_sync(FULL, myb0, hsel | 3), b13 = __shfl_sync(FULL, myb1, hsel | 3);
    int L = hl;
    float ar = (L & 8 ? b10 : b00) * (L & 4 ? b11 : b01) * (L & 2 ? b12 : b02) * (L & 1 ? b13 : b03);
    float ai = 0.f;
#pragma unroll
    for (int l = 0; l < 3; l++) {
#pragma unroll
        for (int w = 0; w < 4; w++)
            rot_shfl(ar, ai, L, &g_rot[(24 + l * 4 + w) * 8], 8 >> w);
        cnot_shfl(ar, ai, L, 8, 4);
        cnot_shfl(ar, ai, L, 4, 2);
        cnot_shfl(ar, ai, L, 2, 1);
    }
    float z0, z1, z2, z3;
    zexp_shfl(ar, ai, L, z0, z1, z2, z3);
    float4 m0 = *(const float4*)(g_M + hl * 4);
    float4 m1 = *(const float4*)(g_M + (hl + 16) * 4);
    out[(size_t)n * DOUT + hl]      = z0 * m0.x + z1 * m0.y + z2 * m0.z + z3 * m0.w + g_C[hl];
    out[(size_t)n * DOUT + hl + 16] = z0 * m1.x + z1 * m1.y + z2 * m1.z + z3 * m1.w + g_C[hl + 16];
}

// ---------------- host ----------------
extern "C" void kernel_launch(void* const* d_in, const int* in_sizes, int n_in,
                              void* d_out, int out_size)
{
    const float* x          = (const float*)d_in[0];
    const float* W_in       = (const float*)d_in[1];
    const float* b_in       = (const float*)d_in[2];
    const float* lin_W      = (const float*)d_in[3];
    const float* lin_b      = (const float*)d_in[4];
    const float* qproj_W    = (const float*)d_in[5];
    const float* qproj_b    = (const float*)d_in[6];
    const float* ent_params = (const float*)d_in[7];
    const float* attq_W     = (const float*)d_in[8];
    const float* attq_b     = (const float*)d_in[9];
    const float* attk_W     = (const float*)d_in[10];
    const float* attk_b     = (const float*)d_in[11];
    const float* att_qp     = (const float*)d_in[12];
    const float* path_params= (const float*)d_in[13];
    const float* path_in_W  = (const float*)d_in[14];
    const float* path_in_b  = (const float*)d_in[15];
    const float* path_out_W = (const float*)d_in[16];
    const float* path_out_b = (const float*)d_in[17];
    const float* out_W      = (const float*)d_in[18];
    const float* out_b      = (const float*)d_in[19];
    const int*   edge_index = (const int*)d_in[20];
    float* out = (float*)d_out;

    int N  = in_sizes[0] / DIN;
    int E  = in_sizes[20] / 2;
    int E2 = E + N;

    float *p_h, *p_hn, *p_xc;
    cudaGetSymbolAddress((void**)&p_h,  g_h);
    cudaGetSymbolAddress((void**)&p_hn, g_hn);
    cudaGetSymbolAddress((void**)&p_xc, g_xc);

    int eblocks = (E2 + 255) / 256;
    int sblocks = (N + 1023) / 1024;
    int nblocks = (N + 15) / 16;       // 16 nodes per 256-thread block (2 per warp)

    // CSR build (g_cnt arrives zeroed: module init on first run, aggfinal restore after)
    count_setup_kernel<<<eblocks, 256>>>(edge_index, E, N,
                                         ent_params, att_qp, path_params,
                                         path_out_W, path_out_b, out_W, out_b);
    scan_kernel<<<sblocks, 1024>>>(N, sblocks);
    fill_kernel<<<eblocks, 256>>>(edge_index, E, N);

    // h0 = relu(x @ W_in^T + b_in)
    gemm64<<<(N + 63) / 64, 128>>>(x, W_in, b_in, p_h, N, DIN, 1, nullptr, nullptr);

    // layer 0
    entqk_kernel<<<nblocks, 256>>>(p_h, 0, attq_W, attq_b, attk_W, attk_b, N);
    gemm64<<<(N + 63) / 64, 128>>>(p_h, lin_W, lin_b, p_xc, N, DH, 0, qproj_W, qproj_b);
    edge_kernel<<<eblocks, 256>>>(E2, 0);

    // layer 1
    aggentqk_kernel<<<nblocks, 256>>>(p_hn, 8,
                                      attq_W + NQ * DH, attq_b + NQ,
                                      attk_W + NQ * DH, attk_b + NQ, N);
    gemm64<<<(N + 63) / 64, 128>>>(p_hn, lin_W + (size_t)DH * DH, lin_b + DH, p_xc, N, DH, 0,
                                   qproj_W + (size_t)DH * NQ, qproj_b + DH);
    edge_kernel<<<eblocks, 256>>>(E2, 1);

    // final
    aggfinal_kernel<<<nblocks, 256>>>(path_in_W, path_in_b, out, N);
}